// round 11
// baseline (speedup 1.0000x reference)
#include <cuda_runtime.h>
#include <math.h>
#include <stdint.h>

#define NB 8
#define RR 256
#define CI 64
#define CO 64
#define MODES 16
#define KX 32
#define GSZ (NB * KX * MODES * CI)   // 262144
#define HSZ (NB * CO * KX * MODES)   // 262144

// ---------------- f32x2 helpers ----------------
__device__ __forceinline__ unsigned long long f2pack(float a, float b) {
    unsigned long long r;
    asm("mov.b64 %0, {%1, %2};" : "=l"(r) : "f"(a), "f"(b));
    return r;
}
__device__ __forceinline__ void f2unpack(unsigned long long v, float& a, float& b) {
    asm("mov.b64 {%0, %1}, %2;" : "=f"(a), "=f"(b) : "l"(v));
}
__device__ __forceinline__ void ffma2(unsigned long long& d, unsigned long long a,
                                      unsigned long long b) {
    asm("fma.rn.f32x2 %0, %1, %2, %3;" : "=l"(d) : "l"(a), "l"(b), "l"(d));
}

// ---------------- tf32 helpers ----------------
__device__ __forceinline__ float tf32f(float f) {
    uint32_t r;
    asm("cvt.rna.tf32.f32 %0, %1;" : "=r"(r) : "f"(f));
    return __uint_as_float(r);
}
__device__ __forceinline__ void mma_tf32(float& c0, float& c1, float& c2, float& c3,
                                         uint32_t a0, uint32_t a1, uint32_t a2, uint32_t a3,
                                         uint32_t b0, uint32_t b1) {
    asm("mma.sync.aligned.m16n8k8.row.col.f32.tf32.tf32.f32 "
        "{%0,%1,%2,%3}, {%4,%5,%6,%7}, {%8,%9}, {%0,%1,%2,%3};"
        : "+f"(c0), "+f"(c1), "+f"(c2), "+f"(c3)
        : "r"(a0), "r"(a1), "r"(a2), "r"(a3), "r"(b0), "r"(b1));
}

// ---------------- device scratch ----------------
__device__ __align__(16) float g_Fx [64 * 256];       // [m][x] m<32:cos m>=32:-sin (kD)
__device__ __align__(16) float g_FxB[256 * 96];       // [x][m'] (kB2)
__device__ __align__(16) float g_Wy2[256 * 32];       // [y][kk] (kA2)
__device__ __align__(16) float g_WyE[32 * 256];       // [k'][y] (kE)
__device__ __align__(16) float g_T   [2 * 2097152];   // G1re | G1im : [b][ky][x][c]
__device__ __align__(16) float g_GreP[2 * GSZ];       // x-half partials
__device__ __align__(16) float g_GimP[2 * GSZ];
__device__ __align__(16) float g_HreP[2 * HSZ];       // i-half partials
__device__ __align__(16) float g_HimP[2 * HSZ];
__device__ __align__(16) float g_Vre[NB * RR * MODES * CO];  // [b][x][ky][o]
__device__ __align__(16) float g_Vim[NB * RR * MODES * CO];

// ---------------- table init ----------------
__global__ void init_tables() {
    int t = blockIdx.x * blockDim.x + threadIdx.x;   // < 24576
    if (t < 64 * 256) {                               // g_Fx
        int m = t >> 8, x = t & 255;
        int j = m & 31;
        int kx = (j < 16) ? j : (224 + j);
        float s, c;
        sincospif((float)((kx * x) & 255) * (1.0f / 128.0f), &s, &c);
        g_Fx[t] = (m < 32) ? c : -s;
    }
    if (t < 256 * 96) {                               // g_FxB
        int x = t / 96, m = t % 96;
        int j = m & 31;
        int kx = (j < 16) ? j : (224 + j);
        float s, c;
        sincospif((float)((kx * x) & 255) * (1.0f / 128.0f), &s, &c);
        g_FxB[t] = (m < 32) ? c : ((m < 64) ? s : -s);
    }
    if (t < 256 * 32) {                               // g_Wy2
        int y = t >> 5, kk = t & 31;
        int ky = kk & 15;
        float s, c;
        sincospif((float)((ky * y) & 255) * (1.0f / 128.0f), &s, &c);
        g_Wy2[t] = (kk < 16) ? c : -s;
    }
    if (t < 32 * 256) {                               // g_WyE
        int kk = t >> 8, y = t & 255;
        int ky = kk & 15;
        float f = (ky == 0) ? 1.0f : 2.0f;
        float s, c;
        sincospif((float)((ky * y) & 255) * (1.0f / 128.0f), &s, &c);
        g_WyE[t] = (kk < 16) ? f * c : -f * s;
    }
}

// ---------------- Stage A': y-direction partial DFT ----------------
__global__ __launch_bounds__(256) void kA2(const float* __restrict__ X) {
    int b  = blockIdx.y;
    int x0 = blockIdx.x * 4;
    __shared__ __align__(16) float Xs[4][32][64];
    __shared__ __align__(16) float Wys[32][32];
    int t  = threadIdx.x;
    int xl = t >> 6;
    int tt = t & 63;
    int kg = tt >> 3;
    int cg = tt & 7;
    int kk0 = kg * 4, c0 = cg * 8;

    unsigned long long acc[4][4];
    #pragma unroll
    for (int i = 0; i < 4; i++)
        #pragma unroll
        for (int p = 0; p < 4; p++) acc[i][p] = 0ull;

    for (int ych = 0; ych < 8; ych++) {
        int y0 = ych * 32;
        #pragma unroll
        for (int l = 0; l < 8; l++) {
            int e = t + l * 256;
            int c4 = e & 15, yy = (e >> 4) & 31, xs = e >> 9;
            *(float4*)&Xs[xs][yy][c4 * 4] =
                *(const float4*)&X[((size_t)((b * 256 + x0 + xs)) * 256 + y0 + yy) * 64 + c4 * 4];
        }
        {
            int kk4 = t & 7, yy = t >> 3;
            *(float4*)&Wys[yy][kk4 * 4] = *(const float4*)&g_Wy2[(y0 + yy) * 32 + kk4 * 4];
        }
        __syncthreads();
        #pragma unroll 8
        for (int yy = 0; yy < 32; yy++) {
            float4 a4 = *(float4*)&Wys[yy][kk0];
            unsigned long long pa0 = f2pack(a4.x, a4.x);
            unsigned long long pa1 = f2pack(a4.y, a4.y);
            unsigned long long pa2 = f2pack(a4.z, a4.z);
            unsigned long long pa3 = f2pack(a4.w, a4.w);
            ulonglong2 b01 = *(ulonglong2*)&Xs[xl][yy][c0];
            ulonglong2 b23 = *(ulonglong2*)&Xs[xl][yy][c0 + 4];
            ffma2(acc[0][0], pa0, b01.x); ffma2(acc[0][1], pa0, b01.y);
            ffma2(acc[0][2], pa0, b23.x); ffma2(acc[0][3], pa0, b23.y);
            ffma2(acc[1][0], pa1, b01.x); ffma2(acc[1][1], pa1, b01.y);
            ffma2(acc[1][2], pa1, b23.x); ffma2(acc[1][3], pa1, b23.y);
            ffma2(acc[2][0], pa2, b01.x); ffma2(acc[2][1], pa2, b01.y);
            ffma2(acc[2][2], pa2, b23.x); ffma2(acc[2][3], pa2, b23.y);
            ffma2(acc[3][0], pa3, b01.x); ffma2(acc[3][1], pa3, b01.y);
            ffma2(acc[3][2], pa3, b23.x); ffma2(acc[3][3], pa3, b23.y);
        }
        __syncthreads();
    }
    int x = x0 + xl;
    #pragma unroll
    for (int j = 0; j < 4; j++) {
        int kk = kk0 + j;
        int ky = kk & 15;
        float* dst = (kk < 16 ? g_T : g_T + 2097152) +
                     ((size_t)((b * 16 + ky) * 256 + x)) * 64 + c0;
        float v[8];
        #pragma unroll
        for (int p = 0; p < 4; p++) f2unpack(acc[j][p], v[2 * p], v[2 * p + 1]);
        *(float4*)&dst[0] = make_float4(v[0], v[1], v[2], v[3]);
        *(float4*)&dst[4] = make_float4(v[4], v[5], v[6], v[7]);
    }
}

// ---------------- Stage B': x-direction partial DFT (x-split halves) ----------------
__global__ __launch_bounds__(128) void kB2() {
    int b = blockIdx.x >> 4, ky = blockIdx.x & 15;
    int xh = blockIdx.y;
    __shared__ __align__(16) float Gr[32 * 64];
    __shared__ __align__(16) float Gi[32 * 64];
    __shared__ __align__(16) float Fxs[32 * 96];
    int t = threadIdx.x;
    int jg = t >> 4, cg = t & 15;
    int j0 = jg * 4, c0 = cg * 4;

    const float* G1r = g_T + ((size_t)(b * 16 + ky)) * 256 * 64;
    const float* G1i = g_T + 2097152 + ((size_t)(b * 16 + ky)) * 256 * 64;

    unsigned long long aR[4][2], aI[4][2];
    #pragma unroll
    for (int i = 0; i < 4; i++) { aR[i][0]=aR[i][1]=aI[i][0]=aI[i][1]=0ull; }

    int xbeg = xh * 128;
    for (int x0 = xbeg; x0 < xbeg + 128; x0 += 32) {
        #pragma unroll
        for (int l = 0; l < 4; l++) {
            int e = t + l * 128;
            ((float4*)Gr)[e] = ((const float4*)(G1r + (size_t)x0 * 64))[e];
            ((float4*)Gi)[e] = ((const float4*)(G1i + (size_t)x0 * 64))[e];
        }
        #pragma unroll
        for (int l = 0; l < 6; l++) {
            int e = t + l * 128;
            ((float4*)Fxs)[e] = ((const float4*)(g_FxB + (size_t)x0 * 96))[e];
        }
        __syncthreads();
        #pragma unroll 4
        for (int xx = 0; xx < 32; xx++) {
            float4 cv = *(float4*)&Fxs[xx * 96 + j0];
            float4 sv = *(float4*)&Fxs[xx * 96 + 32 + j0];
            float4 sn = *(float4*)&Fxs[xx * 96 + 64 + j0];
            ulonglong2 grp = *(ulonglong2*)&Gr[xx * 64 + c0];
            ulonglong2 gip = *(ulonglong2*)&Gi[xx * 64 + c0];
            unsigned long long pc[4] = {f2pack(cv.x,cv.x), f2pack(cv.y,cv.y),
                                        f2pack(cv.z,cv.z), f2pack(cv.w,cv.w)};
            unsigned long long ps[4] = {f2pack(sv.x,sv.x), f2pack(sv.y,sv.y),
                                        f2pack(sv.z,sv.z), f2pack(sv.w,sv.w)};
            unsigned long long pn[4] = {f2pack(sn.x,sn.x), f2pack(sn.y,sn.y),
                                        f2pack(sn.z,sn.z), f2pack(sn.w,sn.w)};
            #pragma unroll
            for (int jj = 0; jj < 4; jj++) {
                ffma2(aR[jj][0], pc[jj], grp.x); ffma2(aR[jj][0], ps[jj], gip.x);
                ffma2(aR[jj][1], pc[jj], grp.y); ffma2(aR[jj][1], ps[jj], gip.y);
                ffma2(aI[jj][0], pc[jj], gip.x); ffma2(aI[jj][0], pn[jj], grp.x);
                ffma2(aI[jj][1], pc[jj], gip.y); ffma2(aI[jj][1], pn[jj], grp.y);
            }
        }
        __syncthreads();
    }
    const float sc = 1.0f / 256.0f;
    float* dstR = g_GreP + (size_t)xh * GSZ;
    float* dstI = g_GimP + (size_t)xh * GSZ;
    #pragma unroll
    for (int jj = 0; jj < 4; jj++) {
        int j = j0 + jj;
        int idx = ((b * KX + j) * MODES + ky) * CI + c0;
        float r0, r1, r2, r3, i0, i1, i2, i3;
        f2unpack(aR[jj][0], r0, r1); f2unpack(aR[jj][1], r2, r3);
        f2unpack(aI[jj][0], i0, i1); f2unpack(aI[jj][1], i2, i3);
        *(float4*)&dstR[idx] = make_float4(r0*sc, r1*sc, r2*sc, r3*sc);
        *(float4*)&dstI[idx] = make_float4(i0*sc, i1*sc, i2*sc, i3*sc);
    }
}

// ---------------- Stage C4: channel mixing, direct sector-aligned fw reads ----------------
// grid (32, 8): j x (bp(0..3) | ih<<2); block 256 = o(64) x kyg(4)
__global__ __launch_bounds__(256) void kC4(const float* __restrict__ fw0,
                                           const float* __restrict__ fw1) {
    __shared__ __align__(16) float Gsr[32 * 36];   // [i][ky*2+b], stride 36
    __shared__ __align__(16) float Gsi[32 * 36];
    int j  = blockIdx.x;
    int bp = blockIdx.y & 3;
    int ih = blockIdx.y >> 2;
    const float* fw = (j < 16) ? fw0 : fw1;
    int jm = j & 15;
    int t = threadIdx.x;
    int o = t & 63, kyg = t >> 6;

    // load G chunk: 2 b x 16 ky x 32 i, summing x-halves
    #pragma unroll
    for (int l = 0; l < 4; l++) {
        int e = t + l * 256;                 // 0..1023
        int i = e & 31, ky = (e >> 5) & 15, bl = e >> 9;
        int gidx = (((bp * 2 + bl) * KX + j) * MODES + ky) * CI + ih * 32 + i;
        Gsr[i * 36 + ky * 2 + bl] = g_GreP[gidx] + g_GreP[GSZ + gidx];
        Gsi[i * 36 + ky * 2 + bl] = g_GimP[gidx] + g_GimP[GSZ + gidx];
    }
    __syncthreads();

    float accR[2][4] = {}, accI[2][4] = {};
    #pragma unroll 4
    for (int i = 0; i < 32; i++) {
        const float* fwp = fw + (((size_t)((ih * 32 + i) * 64 + o) * 16 + jm) * 32) + kyg * 8;
        float4 w01 = *(const float4*)fwp;          // ky0: re,im ; ky1: re,im
        float4 w23 = *(const float4*)(fwp + 4);    // ky2, ky3
        float4 gA = *(float4*)&Gsr[i * 36 + kyg * 8];      // (ky0 b0, ky0 b1, ky1 b0, ky1 b1)
        float4 gB = *(float4*)&Gsr[i * 36 + kyg * 8 + 4];
        float4 hA = *(float4*)&Gsi[i * 36 + kyg * 8];
        float4 hB = *(float4*)&Gsi[i * 36 + kyg * 8 + 4];
        accR[0][0] += gA.x * w01.x - hA.x * w01.y;  accI[0][0] += gA.x * w01.y + hA.x * w01.x;
        accR[1][0] += gA.y * w01.x - hA.y * w01.y;  accI[1][0] += gA.y * w01.y + hA.y * w01.x;
        accR[0][1] += gA.z * w01.z - hA.z * w01.w;  accI[0][1] += gA.z * w01.w + hA.z * w01.z;
        accR[1][1] += gA.w * w01.z - hA.w * w01.w;  accI[1][1] += gA.w * w01.w + hA.w * w01.z;
        accR[0][2] += gB.x * w23.x - hB.x * w23.y;  accI[0][2] += gB.x * w23.y + hB.x * w23.x;
        accR[1][2] += gB.y * w23.x - hB.y * w23.y;  accI[1][2] += gB.y * w23.y + hB.y * w23.x;
        accR[0][3] += gB.z * w23.z - hB.z * w23.w;  accI[0][3] += gB.z * w23.w + hB.z * w23.z;
        accR[1][3] += gB.w * w23.z - hB.w * w23.w;  accI[1][3] += gB.w * w23.w + hB.w * w23.z;
    }
    float* dR = g_HreP + (size_t)ih * HSZ;
    float* dI = g_HimP + (size_t)ih * HSZ;
    #pragma unroll
    for (int bl = 0; bl < 2; bl++) {
        int bg = bp * 2 + bl;
        int hidx = ((bg * CO + o) * KX + j) * MODES + kyg * 4;
        *(float4*)&dR[hidx] = make_float4(accR[bl][0], accR[bl][1], accR[bl][2], accR[bl][3]);
        *(float4*)&dI[hidx] = make_float4(accI[bl][0], accI[bl][1], accI[bl][2], accI[bl][3]);
    }
}

// ---------------- Stage D: inverse x-DFT, layout [b][x][ky][o] ----------------
__global__ __launch_bounds__(256) void kD() {
    int o = blockIdx.x & 63, b = blockIdx.x >> 6;
    __shared__ __align__(16) float hr[KX * MODES];
    __shared__ __align__(16) float hi[KX * MODES];
    int t = threadIdx.x;
    int base = (b * CO + o) * KX * MODES;
    hr[t]       = g_HreP[base + t]       + g_HreP[HSZ + base + t];
    hi[t]       = g_HimP[base + t]       + g_HimP[HSZ + base + t];
    hr[t + 256] = g_HreP[base + t + 256] + g_HreP[HSZ + base + t + 256];
    hi[t + 256] = g_HimP[base + t + 256] + g_HimP[HSZ + base + t + 256];
    __syncthreads();
    int x = t;
    float vr[16] = {}, vi[16] = {};
    for (int j = 0; j < 32; j++) {
        float c =  g_Fx[j * 256 + x];
        float s = -g_Fx[(32 + j) * 256 + x];
        #pragma unroll
        for (int kv = 0; kv < 4; kv++) {
            float4 ar = *(float4*)&hr[j * 16 + kv * 4];
            float4 ai = *(float4*)&hi[j * 16 + kv * 4];
            vr[kv*4+0] += ar.x * c - ai.x * s;  vi[kv*4+0] += ar.x * s + ai.x * c;
            vr[kv*4+1] += ar.y * c - ai.y * s;  vi[kv*4+1] += ar.y * s + ai.y * c;
            vr[kv*4+2] += ar.z * c - ai.z * s;  vi[kv*4+2] += ar.z * s + ai.z * c;
            vr[kv*4+3] += ar.w * c - ai.w * s;  vi[kv*4+3] += ar.w * s + ai.w * c;
        }
    }
    const float sc = 1.0f / 256.0f;
    size_t vbase = ((size_t)(b * 256 + x)) * 16 * 64 + o;
    #pragma unroll
    for (int ky = 0; ky < 16; ky++) {
        g_Vre[vbase + ky * 64] = vr[ky] * sc;
        g_Vim[vbase + ky * 64] = vi[ky] * sc;
    }
}

// ---------------- Stage E: K=96 mma GEMM, wide-LDS fragment layouts ----------------
#define KE_ASTRIDE 104
#define KE_BSTRIDE 72
__global__ __launch_bounds__(256) void kE(const float* __restrict__ X,
                                          const float* __restrict__ Wres,
                                          const float* __restrict__ bres,
                                          float* __restrict__ out) {
    extern __shared__ float sm[];
    float* Ah = sm;                          // [64][104], k-permuted within 8-groups
    float* Al = Ah + 64 * KE_ASTRIDE;
    float* Bh = Al + 64 * KE_ASTRIDE;        // [96][72], [k][g*8+nt]
    float* Bl = Bh + 96 * KE_BSTRIDE;
    float* bias = Bl + 96 * KE_BSTRIDE;      // [64]

    int bi = blockIdx.x;
    int b = bi >> 8, x = bi & 255;
    int t = threadIdx.x;
    int w = t >> 5, lane = t & 31, g = lane >> 2, tg = lane & 3;
    int mt = w & 3, nh = w >> 2;             // 4 m-tiles x 2 n-halves

    // ---- B fill (once): pos = k*72 + (o&7)*8 + (o>>3) ----
    #pragma unroll
    for (int l = 0; l < 16; l++) {
        int e = t + l * 256;                 // 0..4095
        int k = e >> 6, o = e & 63;
        float v = Wres[e];
        float h = tf32f(v);
        int bo = k * KE_BSTRIDE + (o & 7) * 8 + (o >> 3);
        Bh[bo] = h;
        Bl[bo] = tf32f(v - h);
    }
    {
        size_t vb = ((size_t)(b * 256 + x)) * 1024;
        #pragma unroll
        for (int l = 0; l < 8; l++) {
            int e = t + l * 256;             // 0..2047
            int kk = e >> 6, o = e & 63;
            float v = (kk < 16) ? g_Vre[vb + kk * 64 + o]
                                : g_Vim[vb + (kk - 16) * 64 + o];
            float h = tf32f(v);
            int bo = (64 + kk) * KE_BSTRIDE + (o & 7) * 8 + (o >> 3);
            Bh[bo] = h;
            Bl[bo] = tf32f(v - h);
        }
    }
    if (t < 64) bias[t] = bres[t];

    const float* Xrow = X   + ((size_t)(b * 256 + x)) * 16384;
    float*       orow = out + ((size_t)(b * 256 + x)) * 16384;

    for (int ch = 0; ch < 4; ch++) {
        int y0 = ch * 64;
        __syncthreads();
        // ---- A fill: X part (cols 0..63), permuted: col c -> (c&~7)+((c>>2)&1)+(c&3)*2 ----
        #pragma unroll
        for (int l = 0; l < 4; l++) {
            int e = t + l * 256;             // f4 id 0..1023
            int yy = e >> 4, k4 = (e & 15) * 4;
            float4 v = *(const float4*)&Xrow[(size_t)(y0 + yy) * 64 + k4];
            int r = yy * KE_ASTRIDE + (k4 & ~7) + ((k4 & 4) ? 1 : 0);
            float h;
            h = tf32f(v.x); Ah[r]     = h; Al[r]     = tf32f(v.x - h);
            h = tf32f(v.y); Ah[r + 2] = h; Al[r + 2] = tf32f(v.y - h);
            h = tf32f(v.z); Ah[r + 4] = h; Al[r + 4] = tf32f(v.z - h);
            h = tf32f(v.w); Ah[r + 6] = h; Al[r + 6] = tf32f(v.w - h);
        }
        // ---- A fill: WyE part (cols 64..95), same permutation ----
        #pragma unroll
        for (int l = 0; l < 8; l++) {
            int e = t + l * 256;             // 0..2047
            int kk = e >> 6, yy = e & 63;
            float v = g_WyE[kk * 256 + y0 + yy];
            float h = tf32f(v);
            int cp = 64 + (kk & ~7) + (kk & 3) * 2 + ((kk >> 2) & 1);
            int r = yy * KE_ASTRIDE + cp;
            Ah[r] = h;
            Al[r] = tf32f(v - h);
        }
        __syncthreads();

        float c0[4], c1[4], c2[4], c3[4];
        #pragma unroll
        for (int n = 0; n < 4; n++) { c0[n] = c1[n] = c2[n] = c3[n] = 0.f; }

        int ra = (mt * 16 + g) * KE_ASTRIDE;
        #pragma unroll
        for (int k0 = 0; k0 < 96; k0 += 8) {
            float2 h01 = *(float2*)&Ah[ra + k0 + tg * 2];                    // (a0,a2)
            float2 h23 = *(float2*)&Ah[ra + 8 * KE_ASTRIDE + k0 + tg * 2];   // (a1,a3)
            float2 l01 = *(float2*)&Al[ra + k0 + tg * 2];
            float2 l23 = *(float2*)&Al[ra + 8 * KE_ASTRIDE + k0 + tg * 2];
            uint32_t ah0 = __float_as_uint(h01.x), ah2 = __float_as_uint(h01.y);
            uint32_t ah1 = __float_as_uint(h23.x), ah3 = __float_as_uint(h23.y);
            uint32_t al0 = __float_as_uint(l01.x), al2 = __float_as_uint(l01.y);
            uint32_t al1 = __float_as_uint(l23.x), al3 = __float_as_uint(l23.y);
            int boff = g * 8 + nh * 4;
            float4 bh0 = *(float4*)&Bh[(k0 + tg) * KE_BSTRIDE + boff];
            float4 bh1 = *(float4*)&Bh[(k0 + tg + 4) * KE_BSTRIDE + boff];
            float4 bl0 = *(float4*)&Bl[(k0 + tg) * KE_BSTRIDE + boff];
            float4 bl1 = *(float4*)&Bl[(k0 + tg + 4) * KE_BSTRIDE + boff];
            const float* b0p = (const float*)&bh0;
            const float* b1p = (const float*)&bh1;
            const float* c0p = (const float*)&bl0;
            const float* c1p = (const float*)&bl1;
            #pragma unroll
            for (int nl = 0; nl < 4; nl++) {
                uint32_t vb0 = __float_as_uint(b0p[nl]);
                uint32_t vb1 = __float_as_uint(b1p[nl]);
                uint32_t vc0 = __float_as_uint(c0p[nl]);
                uint32_t vc1 = __float_as_uint(c1p[nl]);
                mma_tf32(c0[nl], c1[nl], c2[nl], c3[nl], ah0, ah1, ah2, ah3, vb0, vb1);
                mma_tf32(c0[nl], c1[nl], c2[nl], c3[nl], ah0, ah1, ah2, ah3, vc0, vc1);
                mma_tf32(c0[nl], c1[nl], c2[nl], c3[nl], al0, al1, al2, al3, vb0, vb1);
            }
        }
        // ---- epilogue ----
        int row0 = y0 + mt * 16 + g;
        int row1 = row0 + 8;
        #pragma unroll
        for (int nl = 0; nl < 4; nl++) {
            int col = (nh * 4 + nl) * 8 + 2 * tg;
            float b0v = bias[col], b1v = bias[col + 1];
            float z0 = c0[nl] + b0v, z1 = c1[nl] + b1v;
            float z2 = c2[nl] + b0v, z3 = c3[nl] + b1v;
            z0 = z0 / (1.0f + __expf(-z0));
            z1 = z1 / (1.0f + __expf(-z1));
            z2 = z2 / (1.0f + __expf(-z2));
            z3 = z3 / (1.0f + __expf(-z3));
            *(float2*)&orow[(size_t)row0 * 64 + col] = make_float2(z0, z1);
            *(float2*)&orow[(size_t)row1 * 64 + col] = make_float2(z2, z3);
        }
    }
}

// ---------------- launch ----------------
extern "C" void kernel_launch(void* const* d_in, const int* in_sizes, int n_in,
                              void* d_out, int out_size) {
    const float* X    = (const float*)d_in[0];
    const float* Wres = (const float*)d_in[1];
    const float* bres = (const float*)d_in[2];
    const float* fw0  = (const float*)d_in[3];
    const float* fw1  = (const float*)d_in[4];
    float* out = (float*)d_out;

    const int kE_smem = (2 * 64 * KE_ASTRIDE + 2 * 96 * KE_BSTRIDE + 64) * 4;
    cudaFuncSetAttribute(kE, cudaFuncAttributeMaxDynamicSharedMemorySize, kE_smem);

    init_tables<<<96, 256>>>();
    kA2<<<dim3(64, NB), 256>>>(X);
    kB2<<<dim3(128, 2), 128>>>();
    kC4<<<dim3(32, 8), 256>>>(fw0, fw1);
    kD<<<NB * CO, 256>>>();
    kE<<<NB * RR, 256, kE_smem>>>(X, Wres, bres, out);
}

// round 12
// speedup vs baseline: 1.1668x; 1.1668x over previous
#include <cuda_runtime.h>
#include <math.h>
#include <stdint.h>

#define NB 8
#define RR 256
#define CI 64
#define CO 64
#define MODES 16
#define KX 32
#define GSZ (NB * KX * MODES * CI)   // 262144
#define HSZ (NB * CO * KX * MODES)   // 262144

// ---------------- f32x2 helpers ----------------
__device__ __forceinline__ unsigned long long f2pack(float a, float b) {
    unsigned long long r;
    asm("mov.b64 %0, {%1, %2};" : "=l"(r) : "f"(a), "f"(b));
    return r;
}
__device__ __forceinline__ void f2unpack(unsigned long long v, float& a, float& b) {
    asm("mov.b64 {%0, %1}, %2;" : "=f"(a), "=f"(b) : "l"(v));
}
__device__ __forceinline__ void ffma2(unsigned long long& d, unsigned long long a,
                                      unsigned long long b) {
    asm("fma.rn.f32x2 %0, %1, %2, %3;" : "=l"(d) : "l"(a), "l"(b), "l"(d));
}

// ---------------- tf32 helpers ----------------
__device__ __forceinline__ float tf32f(float f) {
    uint32_t r;
    asm("cvt.rna.tf32.f32 %0, %1;" : "=r"(r) : "f"(f));
    return __uint_as_float(r);
}
__device__ __forceinline__ void mma_tf32(float& c0, float& c1, float& c2, float& c3,
                                         uint32_t a0, uint32_t a1, uint32_t a2, uint32_t a3,
                                         uint32_t b0, uint32_t b1) {
    asm("mma.sync.aligned.m16n8k8.row.col.f32.tf32.tf32.f32 "
        "{%0,%1,%2,%3}, {%4,%5,%6,%7}, {%8,%9}, {%0,%1,%2,%3};"
        : "+f"(c0), "+f"(c1), "+f"(c2), "+f"(c3)
        : "r"(a0), "r"(a1), "r"(a2), "r"(a3), "r"(b0), "r"(b1));
}

// ---------------- device scratch ----------------
__device__ __align__(16) float g_Fx [64 * 256];       // [m][x] m<32:cos m>=32:-sin (kD)
__device__ __align__(16) float g_FxB[256 * 96];       // [x][m'] (kB2)
__device__ __align__(16) float g_Wy2[256 * 32];       // [y][kk] (kA2)
__device__ __align__(16) float g_WyE[32 * 256];       // [k'][y] (kE)
__device__ __align__(16) float g_T   [2 * 2097152];   // G1re | G1im : [b][ky][x][c]
__device__ __align__(16) float g_GreP[2 * GSZ];       // x-half partials
__device__ __align__(16) float g_GimP[2 * GSZ];
__device__ __align__(16) float g_HreP[2 * HSZ];       // i-half partials
__device__ __align__(16) float g_HimP[2 * HSZ];
__device__ __align__(16) float g_Vre[NB * RR * MODES * CO];  // [b][x][ky][o]
__device__ __align__(16) float g_Vim[NB * RR * MODES * CO];

// ---------------- table init ----------------
__global__ void init_tables() {
    int t = blockIdx.x * blockDim.x + threadIdx.x;   // < 24576
    if (t < 64 * 256) {                               // g_Fx
        int m = t >> 8, x = t & 255;
        int j = m & 31;
        int kx = (j < 16) ? j : (224 + j);
        float s, c;
        sincospif((float)((kx * x) & 255) * (1.0f / 128.0f), &s, &c);
        g_Fx[t] = (m < 32) ? c : -s;
    }
    if (t < 256 * 96) {                               // g_FxB
        int x = t / 96, m = t % 96;
        int j = m & 31;
        int kx = (j < 16) ? j : (224 + j);
        float s, c;
        sincospif((float)((kx * x) & 255) * (1.0f / 128.0f), &s, &c);
        g_FxB[t] = (m < 32) ? c : ((m < 64) ? s : -s);
    }
    if (t < 256 * 32) {                               // g_Wy2
        int y = t >> 5, kk = t & 31;
        int ky = kk & 15;
        float s, c;
        sincospif((float)((ky * y) & 255) * (1.0f / 128.0f), &s, &c);
        g_Wy2[t] = (kk < 16) ? c : -s;
    }
    if (t < 32 * 256) {                               // g_WyE
        int kk = t >> 8, y = t & 255;
        int ky = kk & 15;
        float f = (ky == 0) ? 1.0f : 2.0f;
        float s, c;
        sincospif((float)((ky * y) & 255) * (1.0f / 128.0f), &s, &c);
        g_WyE[t] = (kk < 16) ? f * c : -f * s;
    }
}

// ---------------- Stage A': y-direction partial DFT ----------------
__global__ __launch_bounds__(256) void kA2(const float* __restrict__ X) {
    int b  = blockIdx.y;
    int x0 = blockIdx.x * 4;
    __shared__ __align__(16) float Xs[4][32][64];
    __shared__ __align__(16) float Wys[32][32];
    int t  = threadIdx.x;
    int xl = t >> 6;
    int tt = t & 63;
    int kg = tt >> 3;
    int cg = tt & 7;
    int kk0 = kg * 4, c0 = cg * 8;

    unsigned long long acc[4][4];
    #pragma unroll
    for (int i = 0; i < 4; i++)
        #pragma unroll
        for (int p = 0; p < 4; p++) acc[i][p] = 0ull;

    for (int ych = 0; ych < 8; ych++) {
        int y0 = ych * 32;
        #pragma unroll
        for (int l = 0; l < 8; l++) {
            int e = t + l * 256;
            int c4 = e & 15, yy = (e >> 4) & 31, xs = e >> 9;
            *(float4*)&Xs[xs][yy][c4 * 4] =
                *(const float4*)&X[((size_t)((b * 256 + x0 + xs)) * 256 + y0 + yy) * 64 + c4 * 4];
        }
        {
            int kk4 = t & 7, yy = t >> 3;
            *(float4*)&Wys[yy][kk4 * 4] = *(const float4*)&g_Wy2[(y0 + yy) * 32 + kk4 * 4];
        }
        __syncthreads();
        #pragma unroll 8
        for (int yy = 0; yy < 32; yy++) {
            float4 a4 = *(float4*)&Wys[yy][kk0];
            unsigned long long pa0 = f2pack(a4.x, a4.x);
            unsigned long long pa1 = f2pack(a4.y, a4.y);
            unsigned long long pa2 = f2pack(a4.z, a4.z);
            unsigned long long pa3 = f2pack(a4.w, a4.w);
            ulonglong2 b01 = *(ulonglong2*)&Xs[xl][yy][c0];
            ulonglong2 b23 = *(ulonglong2*)&Xs[xl][yy][c0 + 4];
            ffma2(acc[0][0], pa0, b01.x); ffma2(acc[0][1], pa0, b01.y);
            ffma2(acc[0][2], pa0, b23.x); ffma2(acc[0][3], pa0, b23.y);
            ffma2(acc[1][0], pa1, b01.x); ffma2(acc[1][1], pa1, b01.y);
            ffma2(acc[1][2], pa1, b23.x); ffma2(acc[1][3], pa1, b23.y);
            ffma2(acc[2][0], pa2, b01.x); ffma2(acc[2][1], pa2, b01.y);
            ffma2(acc[2][2], pa2, b23.x); ffma2(acc[2][3], pa2, b23.y);
            ffma2(acc[3][0], pa3, b01.x); ffma2(acc[3][1], pa3, b01.y);
            ffma2(acc[3][2], pa3, b23.x); ffma2(acc[3][3], pa3, b23.y);
        }
        __syncthreads();
    }
    int x = x0 + xl;
    #pragma unroll
    for (int j = 0; j < 4; j++) {
        int kk = kk0 + j;
        int ky = kk & 15;
        float* dst = (kk < 16 ? g_T : g_T + 2097152) +
                     ((size_t)((b * 16 + ky) * 256 + x)) * 64 + c0;
        float v[8];
        #pragma unroll
        for (int p = 0; p < 4; p++) f2unpack(acc[j][p], v[2 * p], v[2 * p + 1]);
        *(float4*)&dst[0] = make_float4(v[0], v[1], v[2], v[3]);
        *(float4*)&dst[4] = make_float4(v[4], v[5], v[6], v[7]);
    }
}

// ---------------- Stage B': x-direction partial DFT (x-split halves) ----------------
__global__ __launch_bounds__(128) void kB2() {
    int b = blockIdx.x >> 4, ky = blockIdx.x & 15;
    int xh = blockIdx.y;
    __shared__ __align__(16) float Gr[32 * 64];
    __shared__ __align__(16) float Gi[32 * 64];
    __shared__ __align__(16) float Fxs[32 * 96];
    int t = threadIdx.x;
    int jg = t >> 4, cg = t & 15;
    int j0 = jg * 4, c0 = cg * 4;

    const float* G1r = g_T + ((size_t)(b * 16 + ky)) * 256 * 64;
    const float* G1i = g_T + 2097152 + ((size_t)(b * 16 + ky)) * 256 * 64;

    unsigned long long aR[4][2], aI[4][2];
    #pragma unroll
    for (int i = 0; i < 4; i++) { aR[i][0]=aR[i][1]=aI[i][0]=aI[i][1]=0ull; }

    int xbeg = xh * 128;
    for (int x0 = xbeg; x0 < xbeg + 128; x0 += 32) {
        #pragma unroll
        for (int l = 0; l < 4; l++) {
            int e = t + l * 128;
            ((float4*)Gr)[e] = ((const float4*)(G1r + (size_t)x0 * 64))[e];
            ((float4*)Gi)[e] = ((const float4*)(G1i + (size_t)x0 * 64))[e];
        }
        #pragma unroll
        for (int l = 0; l < 6; l++) {
            int e = t + l * 128;
            ((float4*)Fxs)[e] = ((const float4*)(g_FxB + (size_t)x0 * 96))[e];
        }
        __syncthreads();
        #pragma unroll 4
        for (int xx = 0; xx < 32; xx++) {
            float4 cv = *(float4*)&Fxs[xx * 96 + j0];
            float4 sv = *(float4*)&Fxs[xx * 96 + 32 + j0];
            float4 sn = *(float4*)&Fxs[xx * 96 + 64 + j0];
            ulonglong2 grp = *(ulonglong2*)&Gr[xx * 64 + c0];
            ulonglong2 gip = *(ulonglong2*)&Gi[xx * 64 + c0];
            unsigned long long pc[4] = {f2pack(cv.x,cv.x), f2pack(cv.y,cv.y),
                                        f2pack(cv.z,cv.z), f2pack(cv.w,cv.w)};
            unsigned long long ps[4] = {f2pack(sv.x,sv.x), f2pack(sv.y,sv.y),
                                        f2pack(sv.z,sv.z), f2pack(sv.w,sv.w)};
            unsigned long long pn[4] = {f2pack(sn.x,sn.x), f2pack(sn.y,sn.y),
                                        f2pack(sn.z,sn.z), f2pack(sn.w,sn.w)};
            #pragma unroll
            for (int jj = 0; jj < 4; jj++) {
                ffma2(aR[jj][0], pc[jj], grp.x); ffma2(aR[jj][0], ps[jj], gip.x);
                ffma2(aR[jj][1], pc[jj], grp.y); ffma2(aR[jj][1], ps[jj], gip.y);
                ffma2(aI[jj][0], pc[jj], gip.x); ffma2(aI[jj][0], pn[jj], grp.x);
                ffma2(aI[jj][1], pc[jj], gip.y); ffma2(aI[jj][1], pn[jj], grp.y);
            }
        }
        __syncthreads();
    }
    const float sc = 1.0f / 256.0f;
    float* dstR = g_GreP + (size_t)xh * GSZ;
    float* dstI = g_GimP + (size_t)xh * GSZ;
    #pragma unroll
    for (int jj = 0; jj < 4; jj++) {
        int j = j0 + jj;
        int idx = ((b * KX + j) * MODES + ky) * CI + c0;
        float r0, r1, r2, r3, i0, i1, i2, i3;
        f2unpack(aR[jj][0], r0, r1); f2unpack(aR[jj][1], r2, r3);
        f2unpack(aI[jj][0], i0, i1); f2unpack(aI[jj][1], i2, i3);
        *(float4*)&dstR[idx] = make_float4(r0*sc, r1*sc, r2*sc, r3*sc);
        *(float4*)&dstI[idx] = make_float4(i0*sc, i1*sc, i2*sc, i3*sc);
    }
}

// ---------------- Stage C4: channel mixing, direct sector-aligned fw reads ----------------
// grid (32, 8): j x (bp(0..3) | ih<<2); block 256 = o(64) x kyg(4)
__global__ __launch_bounds__(256) void kC4(const float* __restrict__ fw0,
                                           const float* __restrict__ fw1) {
    __shared__ __align__(16) float Gsr[32 * 36];   // [i][ky*2+b], stride 36
    __shared__ __align__(16) float Gsi[32 * 36];
    int j  = blockIdx.x;
    int bp = blockIdx.y & 3;
    int ih = blockIdx.y >> 2;
    const float* fw = (j < 16) ? fw0 : fw1;
    int jm = j & 15;
    int t = threadIdx.x;
    int o = t & 63, kyg = t >> 6;

    // load G chunk: 2 b x 16 ky x 32 i, summing x-halves
    #pragma unroll
    for (int l = 0; l < 4; l++) {
        int e = t + l * 256;                 // 0..1023
        int i = e & 31, ky = (e >> 5) & 15, bl = e >> 9;
        int gidx = (((bp * 2 + bl) * KX + j) * MODES + ky) * CI + ih * 32 + i;
        Gsr[i * 36 + ky * 2 + bl] = g_GreP[gidx] + g_GreP[GSZ + gidx];
        Gsi[i * 36 + ky * 2 + bl] = g_GimP[gidx] + g_GimP[GSZ + gidx];
    }
    __syncthreads();

    float accR[2][4] = {}, accI[2][4] = {};
    #pragma unroll 4
    for (int i = 0; i < 32; i++) {
        const float* fwp = fw + (((size_t)((ih * 32 + i) * 64 + o) * 16 + jm) * 32) + kyg * 8;
        float4 w01 = *(const float4*)fwp;          // ky0: re,im ; ky1: re,im
        float4 w23 = *(const float4*)(fwp + 4);    // ky2, ky3
        float4 gA = *(float4*)&Gsr[i * 36 + kyg * 8];      // (ky0 b0, ky0 b1, ky1 b0, ky1 b1)
        float4 gB = *(float4*)&Gsr[i * 36 + kyg * 8 + 4];
        float4 hA = *(float4*)&Gsi[i * 36 + kyg * 8];
        float4 hB = *(float4*)&Gsi[i * 36 + kyg * 8 + 4];
        accR[0][0] += gA.x * w01.x - hA.x * w01.y;  accI[0][0] += gA.x * w01.y + hA.x * w01.x;
        accR[1][0] += gA.y * w01.x - hA.y * w01.y;  accI[1][0] += gA.y * w01.y + hA.y * w01.x;
        accR[0][1] += gA.z * w01.z - hA.z * w01.w;  accI[0][1] += gA.z * w01.w + hA.z * w01.z;
        accR[1][1] += gA.w * w01.z - hA.w * w01.w;  accI[1][1] += gA.w * w01.w + hA.w * w01.z;
        accR[0][2] += gB.x * w23.x - hB.x * w23.y;  accI[0][2] += gB.x * w23.y + hB.x * w23.x;
        accR[1][2] += gB.y * w23.x - hB.y * w23.y;  accI[1][2] += gB.y * w23.y + hB.y * w23.x;
        accR[0][3] += gB.z * w23.z - hB.z * w23.w;  accI[0][3] += gB.z * w23.w + hB.z * w23.z;
        accR[1][3] += gB.w * w23.z - hB.w * w23.w;  accI[1][3] += gB.w * w23.w + hB.w * w23.z;
    }
    float* dR = g_HreP + (size_t)ih * HSZ;
    float* dI = g_HimP + (size_t)ih * HSZ;
    #pragma unroll
    for (int bl = 0; bl < 2; bl++) {
        int bg = bp * 2 + bl;
        int hidx = ((bg * CO + o) * KX + j) * MODES + kyg * 4;
        *(float4*)&dR[hidx] = make_float4(accR[bl][0], accR[bl][1], accR[bl][2], accR[bl][3]);
        *(float4*)&dI[hidx] = make_float4(accI[bl][0], accI[bl][1], accI[bl][2], accI[bl][3]);
    }
}

// ---------------- Stage D: inverse x-DFT, layout [b][x][ky][o] ----------------
__global__ __launch_bounds__(256) void kD() {
    int o = blockIdx.x & 63, b = blockIdx.x >> 6;
    __shared__ __align__(16) float hr[KX * MODES];
    __shared__ __align__(16) float hi[KX * MODES];
    int t = threadIdx.x;
    int base = (b * CO + o) * KX * MODES;
    hr[t]       = g_HreP[base + t]       + g_HreP[HSZ + base + t];
    hi[t]       = g_HimP[base + t]       + g_HimP[HSZ + base + t];
    hr[t + 256] = g_HreP[base + t + 256] + g_HreP[HSZ + base + t + 256];
    hi[t + 256] = g_HimP[base + t + 256] + g_HimP[HSZ + base + t + 256];
    __syncthreads();
    int x = t;
    float vr[16] = {}, vi[16] = {};
    for (int j = 0; j < 32; j++) {
        float c =  g_Fx[j * 256 + x];
        float s = -g_Fx[(32 + j) * 256 + x];
        #pragma unroll
        for (int kv = 0; kv < 4; kv++) {
            float4 ar = *(float4*)&hr[j * 16 + kv * 4];
            float4 ai = *(float4*)&hi[j * 16 + kv * 4];
            vr[kv*4+0] += ar.x * c - ai.x * s;  vi[kv*4+0] += ar.x * s + ai.x * c;
            vr[kv*4+1] += ar.y * c - ai.y * s;  vi[kv*4+1] += ar.y * s + ai.y * c;
            vr[kv*4+2] += ar.z * c - ai.z * s;  vi[kv*4+2] += ar.z * s + ai.z * c;
            vr[kv*4+3] += ar.w * c - ai.w * s;  vi[kv*4+3] += ar.w * s + ai.w * c;
        }
    }
    const float sc = 1.0f / 256.0f;
    size_t vbase = ((size_t)(b * 256 + x)) * 16 * 64 + o;
    #pragma unroll
    for (int ky = 0; ky < 16; ky++) {
        g_Vre[vbase + ky * 64] = vr[ky] * sc;
        g_Vim[vbase + ky * 64] = vi[ky] * sc;
    }
}

// ---------------- Stage E: unified K=96 GEMM (R7 proven version) ----------------
#define KE_ASTRIDE 100
#define KE_BSTRIDE 72
__global__ __launch_bounds__(256) void kE(const float* __restrict__ X,
                                          const float* __restrict__ Wres,
                                          const float* __restrict__ bres,
                                          float* __restrict__ out) {
    extern __shared__ float sm[];
    float* Ah = sm;                          // [64][100]
    float* Al = Ah + 64 * KE_ASTRIDE;
    float* Bh = Al + 64 * KE_ASTRIDE;        // [96][72]
    float* Bl = Bh + 96 * KE_BSTRIDE;
    float* bias = Bl + 96 * KE_BSTRIDE;      // [64]

    int bi = blockIdx.x;
    int b = bi >> 8, x = bi & 255;
    int t = threadIdx.x;
    int w = t >> 5, lane = t & 31, g = lane >> 2, tg = lane & 3;
    int mt = w & 3, nh = w >> 2;             // 4 m-tiles x 2 n-halves

    // ---- B fill (once) ----
    #pragma unroll
    for (int l = 0; l < 16; l++) {
        int e = t + l * 256;                 // 0..4095
        int k = e >> 6, o = e & 63;
        float v = Wres[e];
        float h = tf32f(v);
        Bh[k * KE_BSTRIDE + o] = h;
        Bl[k * KE_BSTRIDE + o] = tf32f(v - h);
    }
    {
        size_t vb = ((size_t)(b * 256 + x)) * 1024;
        #pragma unroll
        for (int l = 0; l < 8; l++) {
            int e = t + l * 256;             // 0..2047
            int kk = e >> 6, o = e & 63;
            float v = (kk < 16) ? g_Vre[vb + kk * 64 + o]
                                : g_Vim[vb + (kk - 16) * 64 + o];
            float h = tf32f(v);
            int r = (64 + kk) * KE_BSTRIDE + o;
            Bh[r] = h;
            Bl[r] = tf32f(v - h);
        }
    }
    if (t < 64) bias[t] = bres[t];

    const float* Xrow = X   + ((size_t)(b * 256 + x)) * 16384;
    float*       orow = out + ((size_t)(b * 256 + x)) * 16384;
    const uint32_t* Ahp = (const uint32_t*)Ah;
    const uint32_t* Alp = (const uint32_t*)Al;
    const uint32_t* Bhp = (const uint32_t*)Bh;
    const uint32_t* Blp = (const uint32_t*)Bl;

    for (int ch = 0; ch < 4; ch++) {
        int y0 = ch * 64;
        __syncthreads();
        // ---- A fill: X part (cols 0..63), 64 rows ----
        #pragma unroll
        for (int l = 0; l < 4; l++) {
            int e = t + l * 256;             // f4 id 0..1023
            int yy = e >> 4, k4 = (e & 15) * 4;
            float4 v = *(const float4*)&Xrow[(size_t)(y0 + yy) * 64 + k4];
            int r = yy * KE_ASTRIDE + k4;
            float h;
            h = tf32f(v.x); Ah[r]     = h; Al[r]     = tf32f(v.x - h);
            h = tf32f(v.y); Ah[r + 1] = h; Al[r + 1] = tf32f(v.y - h);
            h = tf32f(v.z); Ah[r + 2] = h; Al[r + 2] = tf32f(v.z - h);
            h = tf32f(v.w); Ah[r + 3] = h; Al[r + 3] = tf32f(v.w - h);
        }
        // ---- A fill: WyE part (cols 64..95) ----
        #pragma unroll
        for (int l = 0; l < 8; l++) {
            int e = t + l * 256;             // 0..2047
            int kk = e >> 6, yy = e & 63;
            float v = g_WyE[kk * 256 + y0 + yy];
            float h = tf32f(v);
            int r = yy * KE_ASTRIDE + 64 + kk;
            Ah[r] = h;
            Al[r] = tf32f(v - h);
        }
        __syncthreads();

        float c0[4], c1[4], c2[4], c3[4];
        #pragma unroll
        for (int n = 0; n < 4; n++) { c0[n] = c1[n] = c2[n] = c3[n] = 0.f; }

        int ra = (mt * 16 + g) * KE_ASTRIDE;
        #pragma unroll
        for (int k0 = 0; k0 < 96; k0 += 8) {
            uint32_t ah0 = Ahp[ra + k0 + tg];
            uint32_t ah1 = Ahp[ra + 8 * KE_ASTRIDE + k0 + tg];
            uint32_t ah2 = Ahp[ra + k0 + tg + 4];
            uint32_t ah3 = Ahp[ra + 8 * KE_ASTRIDE + k0 + tg + 4];
            uint32_t al0 = Alp[ra + k0 + tg];
            uint32_t al1 = Alp[ra + 8 * KE_ASTRIDE + k0 + tg];
            uint32_t al2 = Alp[ra + k0 + tg + 4];
            uint32_t al3 = Alp[ra + 8 * KE_ASTRIDE + k0 + tg + 4];
            int rb0 = (k0 + tg) * KE_BSTRIDE + g;
            int rb1 = (k0 + tg + 4) * KE_BSTRIDE + g;
            #pragma unroll
            for (int nl = 0; nl < 4; nl++) {
                int nt = nh * 4 + nl;
                uint32_t bh0 = Bhp[rb0 + nt * 8];
                uint32_t bh1 = Bhp[rb1 + nt * 8];
                uint32_t bl0 = Blp[rb0 + nt * 8];
                uint32_t bl1 = Blp[rb1 + nt * 8];
                mma_tf32(c0[nl], c1[nl], c2[nl], c3[nl], ah0, ah1, ah2, ah3, bh0, bh1);
                mma_tf32(c0[nl], c1[nl], c2[nl], c3[nl], ah0, ah1, ah2, ah3, bl0, bl1);
                mma_tf32(c0[nl], c1[nl], c2[nl], c3[nl], al0, al1, al2, al3, bh0, bh1);
            }
        }
        // ---- epilogue ----
        int row0 = y0 + mt * 16 + g;
        int row1 = row0 + 8;
        #pragma unroll
        for (int nl = 0; nl < 4; nl++) {
            int col = (nh * 4 + nl) * 8 + 2 * tg;
            float b0v = bias[col], b1v = bias[col + 1];
            float z0 = c0[nl] + b0v, z1 = c1[nl] + b1v;
            float z2 = c2[nl] + b0v, z3 = c3[nl] + b1v;
            z0 = z0 / (1.0f + __expf(-z0));
            z1 = z1 / (1.0f + __expf(-z1));
            z2 = z2 / (1.0f + __expf(-z2));
            z3 = z3 / (1.0f + __expf(-z3));
            *(float2*)&orow[(size_t)row0 * 64 + col] = make_float2(z0, z1);
            *(float2*)&orow[(size_t)row1 * 64 + col] = make_float2(z2, z3);
        }
    }
}

// ---------------- launch ----------------
extern "C" void kernel_launch(void* const* d_in, const int* in_sizes, int n_in,
                              void* d_out, int out_size) {
    const float* X    = (const float*)d_in[0];
    const float* Wres = (const float*)d_in[1];
    const float* bres = (const float*)d_in[2];
    const float* fw0  = (const float*)d_in[3];
    const float* fw1  = (const float*)d_in[4];
    float* out = (float*)d_out;

    const int kE_smem = (2 * 64 * KE_ASTRIDE + 2 * 96 * KE_BSTRIDE + 64) * 4;
    cudaFuncSetAttribute(kE, cudaFuncAttributeMaxDynamicSharedMemorySize, kE_smem);

    init_tables<<<96, 256>>>();
    kA2<<<dim3(64, NB), 256>>>(X);
    kB2<<<dim3(128, 2), 128>>>();
    kC4<<<dim3(32, 8), 256>>>(fw0, fw1);
    kD<<<NB * CO, 256>>>();
    kE<<<NB * RR, 256, kE_smem>>>(X, Wres, bres, out);
}

// round 14
// speedup vs baseline: 1.1929x; 1.0223x over previous
#include <cuda_runtime.h>
#include <math.h>
#include <stdint.h>

#define NB 8
#define RR 256
#define CI 64
#define CO 64
#define MODES 16
#define KX 32
#define GSZ (NB * KX * MODES * CI)   // 262144
#define HSZ (NB * CO * KX * MODES)   // 262144

// ---------------- f32x2 helpers ----------------
__device__ __forceinline__ unsigned long long f2pack(float a, float b) {
    unsigned long long r;
    asm("mov.b64 %0, {%1, %2};" : "=l"(r) : "f"(a), "f"(b));
    return r;
}
__device__ __forceinline__ void f2unpack(unsigned long long v, float& a, float& b) {
    asm("mov.b64 {%0, %1}, %2;" : "=f"(a), "=f"(b) : "l"(v));
}
__device__ __forceinline__ void ffma2(unsigned long long& d, unsigned long long a,
                                      unsigned long long b) {
    asm("fma.rn.f32x2 %0, %1, %2, %3;" : "=l"(d) : "l"(a), "l"(b), "l"(d));
}

// ---------------- tf32 / mma helpers ----------------
__device__ __forceinline__ float tf32f(float f) {
    uint32_t r;
    asm("cvt.rna.tf32.f32 %0, %1;" : "=r"(r) : "f"(f));
    return __uint_as_float(r);
}
__device__ __forceinline__ void mma_tf32(float& c0, float& c1, float& c2, float& c3,
                                         uint32_t a0, uint32_t a1, uint32_t a2, uint32_t a3,
                                         uint32_t b0, uint32_t b1) {
    asm("mma.sync.aligned.m16n8k8.row.col.f32.tf32.tf32.f32 "
        "{%0,%1,%2,%3}, {%4,%5,%6,%7}, {%8,%9}, {%0,%1,%2,%3};"
        : "+f"(c0), "+f"(c1), "+f"(c2), "+f"(c3)
        : "r"(a0), "r"(a1), "r"(a2), "r"(a3), "r"(b0), "r"(b1));
}
__device__ __forceinline__ void ldsm_x4(uint32_t& r0, uint32_t& r1, uint32_t& r2,
                                        uint32_t& r3, uint32_t addr) {
    asm volatile("ldmatrix.sync.aligned.m8n8.x4.shared.b16 {%0,%1,%2,%3}, [%4];"
                 : "=r"(r0), "=r"(r1), "=r"(r2), "=r"(r3) : "r"(addr));
}

// ---------------- device scratch ----------------
__device__ __align__(16) float g_Fx [64 * 256];
__device__ __align__(16) float g_FxB[256 * 96];
__device__ __align__(16) float g_Wy2[256 * 32];
__device__ __align__(16) float g_WyE[32 * 256];
__device__ __align__(16) float g_T   [2 * 2097152];
__device__ __align__(16) float g_GreP[2 * GSZ];
__device__ __align__(16) float g_GimP[2 * GSZ];
__device__ __align__(16) float g_HreP[2 * HSZ];
__device__ __align__(16) float g_HimP[2 * HSZ];
__device__ __align__(16) float g_Vre[NB * RR * MODES * CO];
__device__ __align__(16) float g_Vim[NB * RR * MODES * CO];

// ---------------- table init ----------------
__global__ void init_tables() {
    int t = blockIdx.x * blockDim.x + threadIdx.x;
    if (t < 64 * 256) {
        int m = t >> 8, x = t & 255;
        int j = m & 31;
        int kx = (j < 16) ? j : (224 + j);
        float s, c;
        sincospif((float)((kx * x) & 255) * (1.0f / 128.0f), &s, &c);
        g_Fx[t] = (m < 32) ? c : -s;
    }
    if (t < 256 * 96) {
        int x = t / 96, m = t % 96;
        int j = m & 31;
        int kx = (j < 16) ? j : (224 + j);
        float s, c;
        sincospif((float)((kx * x) & 255) * (1.0f / 128.0f), &s, &c);
        g_FxB[t] = (m < 32) ? c : ((m < 64) ? s : -s);
    }
    if (t < 256 * 32) {
        int y = t >> 5, kk = t & 31;
        int ky = kk & 15;
        float s, c;
        sincospif((float)((ky * y) & 255) * (1.0f / 128.0f), &s, &c);
        g_Wy2[t] = (kk < 16) ? c : -s;
    }
    if (t < 32 * 256) {
        int kk = t >> 8, y = t & 255;
        int ky = kk & 15;
        float f = (ky == 0) ? 1.0f : 2.0f;
        float s, c;
        sincospif((float)((ky * y) & 255) * (1.0f / 128.0f), &s, &c);
        g_WyE[t] = (kk < 16) ? f * c : -f * s;
    }
}

// ---------------- Stage A': y-direction partial DFT ----------------
__global__ __launch_bounds__(256) void kA2(const float* __restrict__ X) {
    int b  = blockIdx.y;
    int x0 = blockIdx.x * 4;
    __shared__ __align__(16) float Xs[4][32][64];
    __shared__ __align__(16) float Wys[32][32];
    int t  = threadIdx.x;
    int xl = t >> 6;
    int tt = t & 63;
    int kg = tt >> 3;
    int cg = tt & 7;
    int kk0 = kg * 4, c0 = cg * 8;

    unsigned long long acc[4][4];
    #pragma unroll
    for (int i = 0; i < 4; i++)
        #pragma unroll
        for (int p = 0; p < 4; p++) acc[i][p] = 0ull;

    for (int ych = 0; ych < 8; ych++) {
        int y0 = ych * 32;
        #pragma unroll
        for (int l = 0; l < 8; l++) {
            int e = t + l * 256;
            int c4 = e & 15, yy = (e >> 4) & 31, xs = e >> 9;
            *(float4*)&Xs[xs][yy][c4 * 4] =
                *(const float4*)&X[((size_t)((b * 256 + x0 + xs)) * 256 + y0 + yy) * 64 + c4 * 4];
        }
        {
            int kk4 = t & 7, yy = t >> 3;
            *(float4*)&Wys[yy][kk4 * 4] = *(const float4*)&g_Wy2[(y0 + yy) * 32 + kk4 * 4];
        }
        __syncthreads();
        #pragma unroll 8
        for (int yy = 0; yy < 32; yy++) {
            float4 a4 = *(float4*)&Wys[yy][kk0];
            unsigned long long pa0 = f2pack(a4.x, a4.x);
            unsigned long long pa1 = f2pack(a4.y, a4.y);
            unsigned long long pa2 = f2pack(a4.z, a4.z);
            unsigned long long pa3 = f2pack(a4.w, a4.w);
            ulonglong2 b01 = *(ulonglong2*)&Xs[xl][yy][c0];
            ulonglong2 b23 = *(ulonglong2*)&Xs[xl][yy][c0 + 4];
            ffma2(acc[0][0], pa0, b01.x); ffma2(acc[0][1], pa0, b01.y);
            ffma2(acc[0][2], pa0, b23.x); ffma2(acc[0][3], pa0, b23.y);
            ffma2(acc[1][0], pa1, b01.x); ffma2(acc[1][1], pa1, b01.y);
            ffma2(acc[1][2], pa1, b23.x); ffma2(acc[1][3], pa1, b23.y);
            ffma2(acc[2][0], pa2, b01.x); ffma2(acc[2][1], pa2, b01.y);
            ffma2(acc[2][2], pa2, b23.x); ffma2(acc[2][3], pa2, b23.y);
            ffma2(acc[3][0], pa3, b01.x); ffma2(acc[3][1], pa3, b01.y);
            ffma2(acc[3][2], pa3, b23.x); ffma2(acc[3][3], pa3, b23.y);
        }
        __syncthreads();
    }
    int x = x0 + xl;
    #pragma unroll
    for (int j = 0; j < 4; j++) {
        int kk = kk0 + j;
        int ky = kk & 15;
        float* dst = (kk < 16 ? g_T : g_T + 2097152) +
                     ((size_t)((b * 16 + ky) * 256 + x)) * 64 + c0;
        float v[8];
        #pragma unroll
        for (int p = 0; p < 4; p++) f2unpack(acc[j][p], v[2 * p], v[2 * p + 1]);
        *(float4*)&dst[0] = make_float4(v[0], v[1], v[2], v[3]);
        *(float4*)&dst[4] = make_float4(v[4], v[5], v[6], v[7]);
    }
}

// ---------------- Stage B': x-direction partial DFT (x-split halves) ----------------
__global__ __launch_bounds__(128) void kB2() {
    int b = blockIdx.x >> 4, ky = blockIdx.x & 15;
    int xh = blockIdx.y;
    __shared__ __align__(16) float Gr[32 * 64];
    __shared__ __align__(16) float Gi[32 * 64];
    __shared__ __align__(16) float Fxs[32 * 96];
    int t = threadIdx.x;
    int jg = t >> 4, cg = t & 15;
    int j0 = jg * 4, c0 = cg * 4;

    const float* G1r = g_T + ((size_t)(b * 16 + ky)) * 256 * 64;
    const float* G1i = g_T + 2097152 + ((size_t)(b * 16 + ky)) * 256 * 64;

    unsigned long long aR[4][2], aI[4][2];
    #pragma unroll
    for (int i = 0; i < 4; i++) { aR[i][0]=aR[i][1]=aI[i][0]=aI[i][1]=0ull; }

    int xbeg = xh * 128;
    for (int x0 = xbeg; x0 < xbeg + 128; x0 += 32) {
        #pragma unroll
        for (int l = 0; l < 4; l++) {
            int e = t + l * 128;
            ((float4*)Gr)[e] = ((const float4*)(G1r + (size_t)x0 * 64))[e];
            ((float4*)Gi)[e] = ((const float4*)(G1i + (size_t)x0 * 64))[e];
        }
        #pragma unroll
        for (int l = 0; l < 6; l++) {
            int e = t + l * 128;
            ((float4*)Fxs)[e] = ((const float4*)(g_FxB + (size_t)x0 * 96))[e];
        }
        __syncthreads();
        #pragma unroll 4
        for (int xx = 0; xx < 32; xx++) {
            float4 cv = *(float4*)&Fxs[xx * 96 + j0];
            float4 sv = *(float4*)&Fxs[xx * 96 + 32 + j0];
            float4 sn = *(float4*)&Fxs[xx * 96 + 64 + j0];
            ulonglong2 grp = *(ulonglong2*)&Gr[xx * 64 + c0];
            ulonglong2 gip = *(ulonglong2*)&Gi[xx * 64 + c0];
            unsigned long long pc[4] = {f2pack(cv.x,cv.x), f2pack(cv.y,cv.y),
                                        f2pack(cv.z,cv.z), f2pack(cv.w,cv.w)};
            unsigned long long ps[4] = {f2pack(sv.x,sv.x), f2pack(sv.y,sv.y),
                                        f2pack(sv.z,sv.z), f2pack(sv.w,sv.w)};
            unsigned long long pn[4] = {f2pack(sn.x,sn.x), f2pack(sn.y,sn.y),
                                        f2pack(sn.z,sn.z), f2pack(sn.w,sn.w)};
            #pragma unroll
            for (int jj = 0; jj < 4; jj++) {
                ffma2(aR[jj][0], pc[jj], grp.x); ffma2(aR[jj][0], ps[jj], gip.x);
                ffma2(aR[jj][1], pc[jj], grp.y); ffma2(aR[jj][1], ps[jj], gip.y);
                ffma2(aI[jj][0], pc[jj], gip.x); ffma2(aI[jj][0], pn[jj], grp.x);
                ffma2(aI[jj][1], pc[jj], gip.y); ffma2(aI[jj][1], pn[jj], grp.y);
            }
        }
        __syncthreads();
    }
    const float sc = 1.0f / 256.0f;
    float* dstR = g_GreP + (size_t)xh * GSZ;
    float* dstI = g_GimP + (size_t)xh * GSZ;
    #pragma unroll
    for (int jj = 0; jj < 4; jj++) {
        int j = j0 + jj;
        int idx = ((b * KX + j) * MODES + ky) * CI + c0;
        float r0, r1, r2, r3, i0, i1, i2, i3;
        f2unpack(aR[jj][0], r0, r1); f2unpack(aR[jj][1], r2, r3);
        f2unpack(aI[jj][0], i0, i1); f2unpack(aI[jj][1], i2, i3);
        *(float4*)&dstR[idx] = make_float4(r0*sc, r1*sc, r2*sc, r3*sc);
        *(float4*)&dstI[idx] = make_float4(i0*sc, i1*sc, i2*sc, i3*sc);
    }
}

// ---------------- Stage C4: channel mixing, direct sector-aligned fw reads ----------------
__global__ __launch_bounds__(256) void kC4(const float* __restrict__ fw0,
                                           const float* __restrict__ fw1) {
    __shared__ __align__(16) float Gsr[32 * 36];
    __shared__ __align__(16) float Gsi[32 * 36];
    int j  = blockIdx.x;
    int bp = blockIdx.y & 3;
    int ih = blockIdx.y >> 2;
    const float* fw = (j < 16) ? fw0 : fw1;
    int jm = j & 15;
    int t = threadIdx.x;
    int o = t & 63, kyg = t >> 6;

    #pragma unroll
    for (int l = 0; l < 4; l++) {
        int e = t + l * 256;
        int i = e & 31, ky = (e >> 5) & 15, bl = e >> 9;
        int gidx = (((bp * 2 + bl) * KX + j) * MODES + ky) * CI + ih * 32 + i;
        Gsr[i * 36 + ky * 2 + bl] = g_GreP[gidx] + g_GreP[GSZ + gidx];
        Gsi[i * 36 + ky * 2 + bl] = g_GimP[gidx] + g_GimP[GSZ + gidx];
    }
    __syncthreads();

    float accR[2][4] = {}, accI[2][4] = {};
    #pragma unroll 4
    for (int i = 0; i < 32; i++) {
        const float* fwp = fw + (((size_t)((ih * 32 + i) * 64 + o) * 16 + jm) * 32) + kyg * 8;
        float4 w01 = *(const float4*)fwp;
        float4 w23 = *(const float4*)(fwp + 4);
        float4 gA = *(float4*)&Gsr[i * 36 + kyg * 8];
        float4 gB = *(float4*)&Gsr[i * 36 + kyg * 8 + 4];
        float4 hA = *(float4*)&Gsi[i * 36 + kyg * 8];
        float4 hB = *(float4*)&Gsi[i * 36 + kyg * 8 + 4];
        accR[0][0] += gA.x * w01.x - hA.x * w01.y;  accI[0][0] += gA.x * w01.y + hA.x * w01.x;
        accR[1][0] += gA.y * w01.x - hA.y * w01.y;  accI[1][0] += gA.y * w01.y + hA.y * w01.x;
        accR[0][1] += gA.z * w01.z - hA.z * w01.w;  accI[0][1] += gA.z * w01.w + hA.z * w01.z;
        accR[1][1] += gA.w * w01.z - hA.w * w01.w;  accI[1][1] += gA.w * w01.w + hA.w * w01.z;
        accR[0][2] += gB.x * w23.x - hB.x * w23.y;  accI[0][2] += gB.x * w23.y + hB.x * w23.x;
        accR[1][2] += gB.y * w23.x - hB.y * w23.y;  accI[1][2] += gB.y * w23.y + hB.y * w23.x;
        accR[0][3] += gB.z * w23.z - hB.z * w23.w;  accI[0][3] += gB.z * w23.w + hB.z * w23.z;
        accR[1][3] += gB.w * w23.z - hB.w * w23.w;  accI[1][3] += gB.w * w23.w + hB.w * w23.z;
    }
    float* dR = g_HreP + (size_t)ih * HSZ;
    float* dI = g_HimP + (size_t)ih * HSZ;
    #pragma unroll
    for (int bl = 0; bl < 2; bl++) {
        int bg = bp * 2 + bl;
        int hidx = ((bg * CO + o) * KX + j) * MODES + kyg * 4;
        *(float4*)&dR[hidx] = make_float4(accR[bl][0], accR[bl][1], accR[bl][2], accR[bl][3]);
        *(float4*)&dI[hidx] = make_float4(accI[bl][0], accI[bl][1], accI[bl][2], accI[bl][3]);
    }
}

// ---------------- Stage D: inverse x-DFT, layout [b][x][ky][o] ----------------
__global__ __launch_bounds__(256) void kD() {
    int o = blockIdx.x & 63, b = blockIdx.x >> 6;
    __shared__ __align__(16) float hr[KX * MODES];
    __shared__ __align__(16) float hi[KX * MODES];
    int t = threadIdx.x;
    int base = (b * CO + o) * KX * MODES;
    hr[t]       = g_HreP[base + t]       + g_HreP[HSZ + base + t];
    hi[t]       = g_HimP[base + t]       + g_HimP[HSZ + base + t];
    hr[t + 256] = g_HreP[base + t + 256] + g_HreP[HSZ + base + t + 256];
    hi[t + 256] = g_HimP[base + t + 256] + g_HimP[HSZ + base + t + 256];
    __syncthreads();
    int x = t;
    float vr[16] = {}, vi[16] = {};
    for (int j = 0; j < 32; j++) {
        float c =  g_Fx[j * 256 + x];
        float s = -g_Fx[(32 + j) * 256 + x];
        #pragma unroll
        for (int kv = 0; kv < 4; kv++) {
            float4 ar = *(float4*)&hr[j * 16 + kv * 4];
            float4 ai = *(float4*)&hi[j * 16 + kv * 4];
            vr[kv*4+0] += ar.x * c - ai.x * s;  vi[kv*4+0] += ar.x * s + ai.x * c;
            vr[kv*4+1] += ar.y * c - ai.y * s;  vi[kv*4+1] += ar.y * s + ai.y * c;
            vr[kv*4+2] += ar.z * c - ai.z * s;  vi[kv*4+2] += ar.z * s + ai.z * c;
            vr[kv*4+3] += ar.w * c - ai.w * s;  vi[kv*4+3] += ar.w * s + ai.w * c;
        }
    }
    const float sc = 1.0f / 256.0f;
    size_t vbase = ((size_t)(b * 256 + x)) * 16 * 64 + o;
    #pragma unroll
    for (int ky = 0; ky < 16; ky++) {
        g_Vre[vbase + ky * 64] = vr[ky] * sc;
        g_Vim[vbase + ky * 64] = vi[ky] * sc;
    }
}

// ---------------- Stage E: K=96 mma GEMM with ldmatrix fragment loads ----------------
#define KE_ASTRIDE 100
#define KB_STRIDE 100
__global__ __launch_bounds__(256) void kE(const float* __restrict__ X,
                                          const float* __restrict__ Wres,
                                          const float* __restrict__ bres,
                                          float* __restrict__ out) {
    extern __shared__ float sm[];
    float* Ah = sm;                          // [64][100] rows y, cols k
    float* Al = Ah + 64 * KE_ASTRIDE;
    float* Bh = Al + 64 * KE_ASTRIDE;        // [64][100] rows o (n-major), cols k
    float* Bl = Bh + 64 * KB_STRIDE;
    float* bias = Bl + 64 * KB_STRIDE;       // [64]

    int bi = blockIdx.x;
    int b = bi >> 8, x = bi & 255;
    int t = threadIdx.x;
    int w = t >> 5, lane = t & 31, g = lane >> 2, tg = lane & 3;
    int mt = w & 3, nh = w >> 2;             // 4 m-tiles x 2 n-halves

    // ---- B fill (once), n-major: Bh[o][k] ----
    #pragma unroll
    for (int l = 0; l < 16; l++) {
        int e = t + l * 256;                 // 0..4095
        int k = e >> 6, o = e & 63;
        float v = Wres[e];
        float h = tf32f(v);
        Bh[o * KB_STRIDE + k] = h;
        Bl[o * KB_STRIDE + k] = tf32f(v - h);
    }
    {
        size_t vb = ((size_t)(b * 256 + x)) * 1024;
        #pragma unroll
        for (int l = 0; l < 8; l++) {
            int e = t + l * 256;             // 0..2047
            int kk = e >> 6, o = e & 63;
            float v = (kk < 16) ? g_Vre[vb + kk * 64 + o]
                                : g_Vim[vb + (kk - 16) * 64 + o];
            float h = tf32f(v);
            int r = o * KB_STRIDE + 64 + kk;
            Bh[r] = h;
            Bl[r] = tf32f(v - h);
        }
    }
    if (t < 64) bias[t] = bres[t];

    const float* Xrow = X   + ((size_t)(b * 256 + x)) * 16384;
    float*       orow = out + ((size_t)(b * 256 + x)) * 16384;

    // ---- ldmatrix per-lane base addresses (shared-space u32) ----
    uint32_t smb = (uint32_t)__cvta_generic_to_shared(sm);
    int arow = mt * 16 + (lane & 7) + ((lane >> 3) & 1) * 8;
    int acol = (lane & 16) ? 4 : 0;
    uint32_t aOffH = smb + (uint32_t)(arow * KE_ASTRIDE + acol) * 4u;
    uint32_t aOffL = aOffH + (uint32_t)(64 * KE_ASTRIDE) * 4u;
    int brow = nh * 32 + (lane & 7) + ((lane & 16) ? 8 : 0);
    int bcol = (lane & 8) ? 4 : 0;
    uint32_t bOff0H = smb + (uint32_t)(2 * 64 * KE_ASTRIDE) * 4u
                    + (uint32_t)(brow * KB_STRIDE + bcol) * 4u;
    uint32_t bOff1H = bOff0H + (uint32_t)(16 * KB_STRIDE) * 4u;
    uint32_t bOff0L = bOff0H + (uint32_t)(64 * KB_STRIDE) * 4u;
    uint32_t bOff1L = bOff1H + (uint32_t)(64 * KB_STRIDE) * 4u;

    for (int ch = 0; ch < 4; ch++) {
        int y0 = ch * 64;
        __syncthreads();
        // ---- A fill: X part (cols 0..63), 64 rows ----
        #pragma unroll
        for (int l = 0; l < 4; l++) {
            int e = t + l * 256;             // f4 id 0..1023
            int yy = e >> 4, k4 = (e & 15) * 4;
            float4 v = *(const float4*)&Xrow[(size_t)(y0 + yy) * 64 + k4];
            int r = yy * KE_ASTRIDE + k4;
            float h;
            h = tf32f(v.x); Ah[r]     = h; Al[r]     = tf32f(v.x - h);
            h = tf32f(v.y); Ah[r + 1] = h; Al[r + 1] = tf32f(v.y - h);
            h = tf32f(v.z); Ah[r + 2] = h; Al[r + 2] = tf32f(v.z - h);
            h = tf32f(v.w); Ah[r + 3] = h; Al[r + 3] = tf32f(v.w - h);
        }
        // ---- A fill: WyE part (cols 64..95) ----
        #pragma unroll
        for (int l = 0; l < 8; l++) {
            int e = t + l * 256;             // 0..2047
            int kk = e >> 6, yy = e & 63;
            float v = g_WyE[kk * 256 + y0 + yy];
            float h = tf32f(v);
            int r = yy * KE_ASTRIDE + 64 + kk;
            Ah[r] = h;
            Al[r] = tf32f(v - h);
        }
        __syncthreads();

        float c0[4], c1[4], c2[4], c3[4];
        #pragma unroll
        for (int n = 0; n < 4; n++) { c0[n] = c1[n] = c2[n] = c3[n] = 0.f; }

        #pragma unroll
        for (int k0 = 0; k0 < 96; k0 += 8) {
            uint32_t koff = (uint32_t)k0 * 4u;
            uint32_t ah[4], al[4], b0h[4], b1h[4], b0l[4], b1l[4];
            ldsm_x4(ah[0], ah[1], ah[2], ah[3], aOffH + koff);
            ldsm_x4(al[0], al[1], al[2], al[3], aOffL + koff);
            ldsm_x4(b0h[0], b0h[1], b0h[2], b0h[3], bOff0H + koff);
            ldsm_x4(b1h[0], b1h[1], b1h[2], b1h[3], bOff1H + koff);
            ldsm_x4(b0l[0], b0l[1], b0l[2], b0l[3], bOff0L + koff);
            ldsm_x4(b1l[0], b1l[1], b1l[2], b1l[3], bOff1L + koff);
            // tiles 0,1 from pair0; tiles 2,3 from pair1
            mma_tf32(c0[0], c1[0], c2[0], c3[0], ah[0], ah[1], ah[2], ah[3], b0h[0], b0h[1]);
            mma_tf32(c0[0], c1[0], c2[0], c3[0], ah[0], ah[1], ah[2], ah[3], b0l[0], b0l[1]);
            mma_tf32(c0[0], c1[0], c2[0], c3[0], al[0], al[1], al[2], al[3], b0h[0], b0h[1]);
            mma_tf32(c0[1], c1[1], c2[1], c3[1], ah[0], ah[1], ah[2], ah[3], b0h[2], b0h[3]);
            mma_tf32(c0[1], c1[1], c2[1], c3[1], ah[0], ah[1], ah[2], ah[3], b0l[2], b0l[3]);
            mma_tf32(c0[1], c1[1], c2[1], c3[1], al[0], al[1], al[2], al[3], b0h[2], b0h[3]);
            mma_tf32(c0[2], c1[2], c2[2], c3[2], ah[0], ah[1], ah[2], ah[3], b1h[0], b1h[1]);
            mma_tf32(c0[2], c1[2], c2[2], c3[2], ah[0], ah[1], ah[2], ah[3], b1l[0], b1l[1]);
            mma_tf32(c0[2], c1[2], c2[2], c3[2], al[0], al[1], al[2], al[3], b1h[0], b1h[1]);
            mma_tf32(c0[3], c1[3], c2[3], c3[3], ah[0], ah[1], ah[2], ah[3], b1h[2], b1h[3]);
            mma_tf32(c0[3], c1[3], c2[3], c3[3], ah[0], ah[1], ah[2], ah[3], b1l[2], b1l[3]);
            mma_tf32(c0[3], c1[3], c2[3], c3[3], al[0], al[1], al[2], al[3], b1h[2], b1h[3]);
        }
        // ---- epilogue ----
        int row0 = y0 + mt * 16 + g;
        int row1 = row0 + 8;
        #pragma unroll
        for (int nl = 0; nl < 4; nl++) {
            int col = (nh * 4 + nl) * 8 + 2 * tg;
            float b0v = bias[col], b1v = bias[col + 1];
            float z0 = c0[nl] + b0v, z1 = c1[nl] + b1v;
            float z2 = c2[nl] + b0v, z3 = c3[nl] + b1v;
            z0 = z0 / (1.0f + __expf(-z0));
            z1 = z1 / (1.0f + __expf(-z1));
            z2 = z2 / (1.0f + __expf(-z2));
            z3 = z3 / (1.0f + __expf(-z3));
            *(float2*)&orow[(size_t)row0 * 64 + col] = make_float2(z0, z1);
            *(float2*)&orow[(size_t)row1 * 64 + col] = make_float2(z2, z3);
        }
    }
}

// ---------------- launch ----------------
extern "C" void kernel_launch(void* const* d_in, const int* in_sizes, int n_in,
                              void* d_out, int out_size) {
    const float* X    = (const float*)d_in[0];
    const float* Wres = (const float*)d_in[1];
    const float* bres = (const float*)d_in[2];
    const float* fw0  = (const float*)d_in[3];
    const float* fw1  = (const float*)d_in[4];
    float* out = (float*)d_out;

    const int kE_smem = (2 * 64 * KE_ASTRIDE + 2 * 64 * KB_STRIDE + 64) * 4;
    cudaFuncSetAttribute(kE, cudaFuncAttributeMaxDynamicSharedMemorySize, kE_smem);

    init_tables<<<96, 256>>>();
    kA2<<<dim3(64, NB), 256>>>(X);
    kB2<<<dim3(128, 2), 128>>>();
    kC4<<<dim3(32, 8), 256>>>(fw0, fw1);
    kD<<<NB * CO, 256>>>();
    kE<<<NB * RR, 256, kE_smem>>>(X, Wres, bres, out);
}

// round 16
// speedup vs baseline: 1.3306x; 1.1155x over previous
#include <cuda_runtime.h>
#include <cuda_bf16.h>
#include <math.h>
#include <stdint.h>

#define NB 8
#define RR 256
#define CI 64
#define CO 64
#define MODES 16
#define KX 32
#define GSZ (NB * KX * MODES * CI)   // 262144
#define HSZ (NB * CO * KX * MODES)   // 262144

// ---------------- f32x2 helpers ----------------
__device__ __forceinline__ unsigned long long f2pack(float a, float b) {
    unsigned long long r;
    asm("mov.b64 %0, {%1, %2};" : "=l"(r) : "f"(a), "f"(b));
    return r;
}
__device__ __forceinline__ void f2unpack(unsigned long long v, float& a, float& b) {
    asm("mov.b64 {%0, %1}, %2;" : "=f"(a), "=f"(b) : "l"(v));
}
__device__ __forceinline__ void ffma2(unsigned long long& d, unsigned long long a,
                                      unsigned long long b) {
    asm("fma.rn.f32x2 %0, %1, %2, %3;" : "=l"(d) : "l"(a), "l"(b), "l"(d));
}

// ---------------- bf16 / mma helpers ----------------
__device__ __forceinline__ uint32_t bf2pack(float lo, float hi) {
    uint32_t r;
    asm("cvt.rn.bf16x2.f32 %0, %1, %2;" : "=r"(r) : "f"(hi), "f"(lo));
    return r;
}
__device__ __forceinline__ void mma_bf16(float& c0, float& c1, float& c2, float& c3,
                                         uint32_t a0, uint32_t a1, uint32_t a2, uint32_t a3,
                                         uint32_t b0, uint32_t b1) {
    asm("mma.sync.aligned.m16n8k16.row.col.f32.bf16.bf16.f32 "
        "{%0,%1,%2,%3}, {%4,%5,%6,%7}, {%8,%9}, {%0,%1,%2,%3};"
        : "+f"(c0), "+f"(c1), "+f"(c2), "+f"(c3)
        : "r"(a0), "r"(a1), "r"(a2), "r"(a3), "r"(b0), "r"(b1));
}
__device__ __forceinline__ void ldsm_x4(uint32_t& r0, uint32_t& r1, uint32_t& r2,
                                        uint32_t& r3, uint32_t addr) {
    asm volatile("ldmatrix.sync.aligned.m8n8.x4.shared.b16 {%0,%1,%2,%3}, [%4];"
                 : "=r"(r0), "=r"(r1), "=r"(r2), "=r"(r3) : "r"(addr));
}

// ---------------- device scratch ----------------
__device__ __align__(16) float g_Fx [64 * 256];
__device__ __align__(16) float g_FxB[256 * 96];
__device__ __align__(16) float g_Wy2[256 * 32];
__device__ __align__(16) float g_WyE[32 * 256];
__device__ __align__(16) float g_T   [2 * 2097152];
__device__ __align__(16) float g_GreP[2 * GSZ];
__device__ __align__(16) float g_GimP[2 * GSZ];
__device__ __align__(16) float g_HreP[2 * HSZ];
__device__ __align__(16) float g_HimP[2 * HSZ];
__device__ __align__(16) float g_Vre[NB * RR * MODES * CO];
__device__ __align__(16) float g_Vim[NB * RR * MODES * CO];

// ---------------- table init ----------------
__global__ void init_tables() {
    int t = blockIdx.x * blockDim.x + threadIdx.x;
    if (t < 64 * 256) {
        int m = t >> 8, x = t & 255;
        int j = m & 31;
        int kx = (j < 16) ? j : (224 + j);
        float s, c;
        sincospif((float)((kx * x) & 255) * (1.0f / 128.0f), &s, &c);
        g_Fx[t] = (m < 32) ? c : -s;
    }
    if (t < 256 * 96) {
        int x = t / 96, m = t % 96;
        int j = m & 31;
        int kx = (j < 16) ? j : (224 + j);
        float s, c;
        sincospif((float)((kx * x) & 255) * (1.0f / 128.0f), &s, &c);
        g_FxB[t] = (m < 32) ? c : ((m < 64) ? s : -s);
    }
    if (t < 256 * 32) {
        int y = t >> 5, kk = t & 31;
        int ky = kk & 15;
        float s, c;
        sincospif((float)((ky * y) & 255) * (1.0f / 128.0f), &s, &c);
        g_Wy2[t] = (kk < 16) ? c : -s;
    }
    if (t < 32 * 256) {
        int kk = t >> 8, y = t & 255;
        int ky = kk & 15;
        float f = (ky == 0) ? 1.0f : 2.0f;
        float s, c;
        sincospif((float)((ky * y) & 255) * (1.0f / 128.0f), &s, &c);
        g_WyE[t] = (kk < 16) ? f * c : -f * s;
    }
}

// ---------------- Stage A': y-direction partial DFT ----------------
__global__ __launch_bounds__(256) void kA2(const float* __restrict__ X) {
    int b  = blockIdx.y;
    int x0 = blockIdx.x * 4;
    __shared__ __align__(16) float Xs[4][32][64];
    __shared__ __align__(16) float Wys[32][32];
    int t  = threadIdx.x;
    int xl = t >> 6;
    int tt = t & 63;
    int kg = tt >> 3;
    int cg = tt & 7;
    int kk0 = kg * 4, c0 = cg * 8;

    unsigned long long acc[4][4];
    #pragma unroll
    for (int i = 0; i < 4; i++)
        #pragma unroll
        for (int p = 0; p < 4; p++) acc[i][p] = 0ull;

    for (int ych = 0; ych < 8; ych++) {
        int y0 = ych * 32;
        #pragma unroll
        for (int l = 0; l < 8; l++) {
            int e = t + l * 256;
            int c4 = e & 15, yy = (e >> 4) & 31, xs = e >> 9;
            *(float4*)&Xs[xs][yy][c4 * 4] =
                *(const float4*)&X[((size_t)((b * 256 + x0 + xs)) * 256 + y0 + yy) * 64 + c4 * 4];
        }
        {
            int kk4 = t & 7, yy = t >> 3;
            *(float4*)&Wys[yy][kk4 * 4] = *(const float4*)&g_Wy2[(y0 + yy) * 32 + kk4 * 4];
        }
        __syncthreads();
        #pragma unroll 8
        for (int yy = 0; yy < 32; yy++) {
            float4 a4 = *(float4*)&Wys[yy][kk0];
            unsigned long long pa0 = f2pack(a4.x, a4.x);
            unsigned long long pa1 = f2pack(a4.y, a4.y);
            unsigned long long pa2 = f2pack(a4.z, a4.z);
            unsigned long long pa3 = f2pack(a4.w, a4.w);
            ulonglong2 b01 = *(ulonglong2*)&Xs[xl][yy][c0];
            ulonglong2 b23 = *(ulonglong2*)&Xs[xl][yy][c0 + 4];
            ffma2(acc[0][0], pa0, b01.x); ffma2(acc[0][1], pa0, b01.y);
            ffma2(acc[0][2], pa0, b23.x); ffma2(acc[0][3], pa0, b23.y);
            ffma2(acc[1][0], pa1, b01.x); ffma2(acc[1][1], pa1, b01.y);
            ffma2(acc[1][2], pa1, b23.x); ffma2(acc[1][3], pa1, b23.y);
            ffma2(acc[2][0], pa2, b01.x); ffma2(acc[2][1], pa2, b01.y);
            ffma2(acc[2][2], pa2, b23.x); ffma2(acc[2][3], pa2, b23.y);
            ffma2(acc[3][0], pa3, b01.x); ffma2(acc[3][1], pa3, b01.y);
            ffma2(acc[3][2], pa3, b23.x); ffma2(acc[3][3], pa3, b23.y);
        }
        __syncthreads();
    }
    int x = x0 + xl;
    #pragma unroll
    for (int j = 0; j < 4; j++) {
        int kk = kk0 + j;
        int ky = kk & 15;
        float* dst = (kk < 16 ? g_T : g_T + 2097152) +
                     ((size_t)((b * 16 + ky) * 256 + x)) * 64 + c0;
        float v[8];
        #pragma unroll
        for (int p = 0; p < 4; p++) f2unpack(acc[j][p], v[2 * p], v[2 * p + 1]);
        *(float4*)&dst[0] = make_float4(v[0], v[1], v[2], v[3]);
        *(float4*)&dst[4] = make_float4(v[4], v[5], v[6], v[7]);
    }
}

// ---------------- Stage B': x-direction partial DFT (x-split halves) ----------------
__global__ __launch_bounds__(128) void kB2() {
    int b = blockIdx.x >> 4, ky = blockIdx.x & 15;
    int xh = blockIdx.y;
    __shared__ __align__(16) float Gr[32 * 64];
    __shared__ __align__(16) float Gi[32 * 64];
    __shared__ __align__(16) float Fxs[32 * 96];
    int t = threadIdx.x;
    int jg = t >> 4, cg = t & 15;
    int j0 = jg * 4, c0 = cg * 4;

    const float* G1r = g_T + ((size_t)(b * 16 + ky)) * 256 * 64;
    const float* G1i = g_T + 2097152 + ((size_t)(b * 16 + ky)) * 256 * 64;

    unsigned long long aR[4][2], aI[4][2];
    #pragma unroll
    for (int i = 0; i < 4; i++) { aR[i][0]=aR[i][1]=aI[i][0]=aI[i][1]=0ull; }

    int xbeg = xh * 128;
    for (int x0 = xbeg; x0 < xbeg + 128; x0 += 32) {
        #pragma unroll
        for (int l = 0; l < 4; l++) {
            int e = t + l * 128;
            ((float4*)Gr)[e] = ((const float4*)(G1r + (size_t)x0 * 64))[e];
            ((float4*)Gi)[e] = ((const float4*)(G1i + (size_t)x0 * 64))[e];
        }
        #pragma unroll
        for (int l = 0; l < 6; l++) {
            int e = t + l * 128;
            ((float4*)Fxs)[e] = ((const float4*)(g_FxB + (size_t)x0 * 96))[e];
        }
        __syncthreads();
        #pragma unroll 4
        for (int xx = 0; xx < 32; xx++) {
            float4 cv = *(float4*)&Fxs[xx * 96 + j0];
            float4 sv = *(float4*)&Fxs[xx * 96 + 32 + j0];
            float4 sn = *(float4*)&Fxs[xx * 96 + 64 + j0];
            ulonglong2 grp = *(ulonglong2*)&Gr[xx * 64 + c0];
            ulonglong2 gip = *(ulonglong2*)&Gi[xx * 64 + c0];
            unsigned long long pc[4] = {f2pack(cv.x,cv.x), f2pack(cv.y,cv.y),
                                        f2pack(cv.z,cv.z), f2pack(cv.w,cv.w)};
            unsigned long long ps[4] = {f2pack(sv.x,sv.x), f2pack(sv.y,sv.y),
                                        f2pack(sv.z,sv.z), f2pack(sv.w,sv.w)};
            unsigned long long pn[4] = {f2pack(sn.x,sn.x), f2pack(sn.y,sn.y),
                                        f2pack(sn.z,sn.z), f2pack(sn.w,sn.w)};
            #pragma unroll
            for (int jj = 0; jj < 4; jj++) {
                ffma2(aR[jj][0], pc[jj], grp.x); ffma2(aR[jj][0], ps[jj], gip.x);
                ffma2(aR[jj][1], pc[jj], grp.y); ffma2(aR[jj][1], ps[jj], gip.y);
                ffma2(aI[jj][0], pc[jj], gip.x); ffma2(aI[jj][0], pn[jj], grp.x);
                ffma2(aI[jj][1], pc[jj], gip.y); ffma2(aI[jj][1], pn[jj], grp.y);
            }
        }
        __syncthreads();
    }
    const float sc = 1.0f / 256.0f;
    float* dstR = g_GreP + (size_t)xh * GSZ;
    float* dstI = g_GimP + (size_t)xh * GSZ;
    #pragma unroll
    for (int jj = 0; jj < 4; jj++) {
        int j = j0 + jj;
        int idx = ((b * KX + j) * MODES + ky) * CI + c0;
        float r0, r1, r2, r3, i0, i1, i2, i3;
        f2unpack(aR[jj][0], r0, r1); f2unpack(aR[jj][1], r2, r3);
        f2unpack(aI[jj][0], i0, i1); f2unpack(aI[jj][1], i2, i3);
        *(float4*)&dstR[idx] = make_float4(r0*sc, r1*sc, r2*sc, r3*sc);
        *(float4*)&dstI[idx] = make_float4(i0*sc, i1*sc, i2*sc, i3*sc);
    }
}

// ---------------- Stage C4: channel mixing, direct sector-aligned fw reads ----------------
__global__ __launch_bounds__(256) void kC4(const float* __restrict__ fw0,
                                           const float* __restrict__ fw1) {
    __shared__ __align__(16) float Gsr[32 * 36];
    __shared__ __align__(16) float Gsi[32 * 36];
    int j  = blockIdx.x;
    int bp = blockIdx.y & 3;
    int ih = blockIdx.y >> 2;
    const float* fw = (j < 16) ? fw0 : fw1;
    int jm = j & 15;
    int t = threadIdx.x;
    int o = t & 63, kyg = t >> 6;

    #pragma unroll
    for (int l = 0; l < 4; l++) {
        int e = t + l * 256;
        int i = e & 31, ky = (e >> 5) & 15, bl = e >> 9;
        int gidx = (((bp * 2 + bl) * KX + j) * MODES + ky) * CI + ih * 32 + i;
        Gsr[i * 36 + ky * 2 + bl] = g_GreP[gidx] + g_GreP[GSZ + gidx];
        Gsi[i * 36 + ky * 2 + bl] = g_GimP[gidx] + g_GimP[GSZ + gidx];
    }
    __syncthreads();

    float accR[2][4] = {}, accI[2][4] = {};
    #pragma unroll 4
    for (int i = 0; i < 32; i++) {
        const float* fwp = fw + (((size_t)((ih * 32 + i) * 64 + o) * 16 + jm) * 32) + kyg * 8;
        float4 w01 = *(const float4*)fwp;
        float4 w23 = *(const float4*)(fwp + 4);
        float4 gA = *(float4*)&Gsr[i * 36 + kyg * 8];
        float4 gB = *(float4*)&Gsr[i * 36 + kyg * 8 + 4];
        float4 hA = *(float4*)&Gsi[i * 36 + kyg * 8];
        float4 hB = *(float4*)&Gsi[i * 36 + kyg * 8 + 4];
        accR[0][0] += gA.x * w01.x - hA.x * w01.y;  accI[0][0] += gA.x * w01.y + hA.x * w01.x;
        accR[1][0] += gA.y * w01.x - hA.y * w01.y;  accI[1][0] += gA.y * w01.y + hA.y * w01.x;
        accR[0][1] += gA.z * w01.z - hA.z * w01.w;  accI[0][1] += gA.z * w01.w + hA.z * w01.z;
        accR[1][1] += gA.w * w01.z - hA.w * w01.w;  accI[1][1] += gA.w * w01.w + hA.w * w01.z;
        accR[0][2] += gB.x * w23.x - hB.x * w23.y;  accI[0][2] += gB.x * w23.y + hB.x * w23.x;
        accR[1][2] += gB.y * w23.x - hB.y * w23.y;  accI[1][2] += gB.y * w23.y + hB.y * w23.x;
        accR[0][3] += gB.z * w23.z - hB.z * w23.w;  accI[0][3] += gB.z * w23.w + hB.z * w23.z;
        accR[1][3] += gB.w * w23.z - hB.w * w23.w;  accI[1][3] += gB.w * w23.w + hB.w * w23.z;
    }
    float* dR = g_HreP + (size_t)ih * HSZ;
    float* dI = g_HimP + (size_t)ih * HSZ;
    #pragma unroll
    for (int bl = 0; bl < 2; bl++) {
        int bg = bp * 2 + bl;
        int hidx = ((bg * CO + o) * KX + j) * MODES + kyg * 4;
        *(float4*)&dR[hidx] = make_float4(accR[bl][0], accR[bl][1], accR[bl][2], accR[bl][3]);
        *(float4*)&dI[hidx] = make_float4(accI[bl][0], accI[bl][1], accI[bl][2], accI[bl][3]);
    }
}

// ---------------- Stage D: inverse x-DFT, layout [b][x][ky][o] ----------------
__global__ __launch_bounds__(256) void kD() {
    int o = blockIdx.x & 63, b = blockIdx.x >> 6;
    __shared__ __align__(16) float hr[KX * MODES];
    __shared__ __align__(16) float hi[KX * MODES];
    int t = threadIdx.x;
    int base = (b * CO + o) * KX * MODES;
    hr[t]       = g_HreP[base + t]       + g_HreP[HSZ + base + t];
    hi[t]       = g_HimP[base + t]       + g_HimP[HSZ + base + t];
    hr[t + 256] = g_HreP[base + t + 256] + g_HreP[HSZ + base + t + 256];
    hi[t + 256] = g_HimP[base + t + 256] + g_HimP[HSZ + base + t + 256];
    __syncthreads();
    int x = t;
    float vr[16] = {}, vi[16] = {};
    for (int j = 0; j < 32; j++) {
        float c =  g_Fx[j * 256 + x];
        float s = -g_Fx[(32 + j) * 256 + x];
        #pragma unroll
        for (int kv = 0; kv < 4; kv++) {
            float4 ar = *(float4*)&hr[j * 16 + kv * 4];
            float4 ai = *(float4*)&hi[j * 16 + kv * 4];
            vr[kv*4+0] += ar.x * c - ai.x * s;  vi[kv*4+0] += ar.x * s + ai.x * c;
            vr[kv*4+1] += ar.y * c - ai.y * s;  vi[kv*4+1] += ar.y * s + ai.y * c;
            vr[kv*4+2] += ar.z * c - ai.z * s;  vi[kv*4+2] += ar.z * s + ai.z * c;
            vr[kv*4+3] += ar.w * c - ai.w * s;  vi[kv*4+3] += ar.w * s + ai.w * c;
        }
    }
    const float sc = 1.0f / 256.0f;
    size_t vbase = ((size_t)(b * 256 + x)) * 16 * 64 + o;
    #pragma unroll
    for (int ky = 0; ky < 16; ky++) {
        g_Vre[vbase + ky * 64] = vr[ky] * sc;
        g_Vim[vbase + ky * 64] = vi[ky] * sc;
    }
}

// ---------------- Stage E: K=96 GEMM via 3xBF16 m16n8k16 mma + ldmatrix ----------------
#define KA_ST 104   // bf16 elements per row (208 B: 16B-aligned, conflict-free phases)
__global__ __launch_bounds__(256) void kE(const float* __restrict__ X,
                                          const float* __restrict__ Wres,
                                          const float* __restrict__ bres,
                                          float* __restrict__ out) {
    extern __shared__ __align__(16) char smraw[];
    __nv_bfloat16* Ah = (__nv_bfloat16*)smraw;        // [64][104] rows y, cols k
    __nv_bfloat16* Al = Ah + 64 * KA_ST;
    __nv_bfloat16* Bh = Al + 64 * KA_ST;              // [64][104] rows o, cols k
    __nv_bfloat16* Bl = Bh + 64 * KA_ST;
    float* bias = (float*)(Bl + 64 * KA_ST);          // [64]

    int bi = blockIdx.x;
    int b = bi >> 8, x = bi & 255;
    int t = threadIdx.x;
    int w = t >> 5, lane = t & 31, g = lane >> 2, tg = lane & 3;
    int mt = w & 3, nh = w >> 2;             // 4 m-tiles x 2 n-halves

    // ---- B fill (once), o-major bf16 hi/lo ----
    #pragma unroll
    for (int l = 0; l < 16; l++) {
        int e = t + l * 256;                 // 0..4095 : k = e>>6, o = e&63
        int k = e >> 6, o = e & 63;
        float v = Wres[e];
        __nv_bfloat16 h = __float2bfloat16(v);
        Bh[o * KA_ST + k] = h;
        Bl[o * KA_ST + k] = __float2bfloat16(v - __bfloat162float(h));
    }
    {
        size_t vb = ((size_t)(b * 256 + x)) * 1024;
        #pragma unroll
        for (int l = 0; l < 8; l++) {
            int e = t + l * 256;             // 0..2047
            int kk = e >> 6, o = e & 63;
            float v = (kk < 16) ? g_Vre[vb + kk * 64 + o]
                                : g_Vim[vb + (kk - 16) * 64 + o];
            __nv_bfloat16 h = __float2bfloat16(v);
            Bh[o * KA_ST + 64 + kk] = h;
            Bl[o * KA_ST + 64 + kk] = __float2bfloat16(v - __bfloat162float(h));
        }
    }
    if (t < 64) bias[t] = bres[t];

    const float* Xrow = X   + ((size_t)(b * 256 + x)) * 16384;
    float*       orow = out + ((size_t)(b * 256 + x)) * 16384;

    // ---- ldmatrix per-lane base addresses ----
    uint32_t smb = (uint32_t)__cvta_generic_to_shared(smraw);
    // A (m16n8k16): phases m0..m3 = lanes 0-7/8-15/16-23/24-31
    //   row = mt*16 + (lane & 15), col = (lane & 16) ? 8 : 0
    uint32_t aOffH = smb + (uint32_t)((mt * 16 + (lane & 15)) * KA_ST +
                                      ((lane & 16) ? 8 : 0)) * 2u;
    uint32_t aOffL = aOffH + (uint32_t)(64 * KA_ST) * 2u;
    // B: ldsm#1 covers n-tiles 0,1 ; ldsm#2 tiles 2,3.
    //   row o = nh*32 + (lane&7) + ((lane&16)?8:0) (+16 for second), col = (lane&8)?8:0
    uint32_t brow = (uint32_t)(nh * 32 + (lane & 7) + ((lane & 16) ? 8 : 0));
    uint32_t bcol = (lane & 8) ? 8u : 0u;
    uint32_t bOff0H = smb + (uint32_t)(2 * 64 * KA_ST) * 2u + (brow * KA_ST + bcol) * 2u;
    uint32_t bOff1H = bOff0H + (uint32_t)(16 * KA_ST) * 2u;
    uint32_t bOff0L = bOff0H + (uint32_t)(64 * KA_ST) * 2u;
    uint32_t bOff1L = bOff1H + (uint32_t)(64 * KA_ST) * 2u;

    for (int ch = 0; ch < 4; ch++) {
        int y0 = ch * 64;
        __syncthreads();
        // ---- A fill: X part (cols 0..63), 64 rows, bf16x2 packed stores ----
        #pragma unroll
        for (int l = 0; l < 4; l++) {
            int e = t + l * 256;             // f4 id 0..1023
            int yy = e >> 4, k4 = (e & 15) * 4;
            float4 v = *(const float4*)&Xrow[(size_t)(y0 + yy) * 64 + k4];
            uint32_t* ph = (uint32_t*)&Ah[yy * KA_ST + k4];
            uint32_t* pl = (uint32_t*)&Al[yy * KA_ST + k4];
            uint32_t h01 = bf2pack(v.x, v.y);
            uint32_t h23 = bf2pack(v.z, v.w);
            float hx = __uint_as_float(h01 << 16);
            float hy = __uint_as_float(h01 & 0xFFFF0000u);
            float hz = __uint_as_float(h23 << 16);
            float hw = __uint_as_float(h23 & 0xFFFF0000u);
            ph[0] = h01; ph[1] = h23;
            pl[0] = bf2pack(v.x - hx, v.y - hy);
            pl[1] = bf2pack(v.z - hz, v.w - hw);
        }
        // ---- A fill: WyE part (cols 64..95) ----
        #pragma unroll
        for (int l = 0; l < 8; l++) {
            int e = t + l * 256;             // 0..2047
            int kk = e >> 6, yy = e & 63;
            float v = g_WyE[kk * 256 + y0 + yy];
            __nv_bfloat16 h = __float2bfloat16(v);
            Ah[yy * KA_ST + 64 + kk] = h;
            Al[yy * KA_ST + 64 + kk] = __float2bfloat16(v - __bfloat162float(h));
        }
        __syncthreads();

        float c0[4], c1[4], c2[4], c3[4];
        #pragma unroll
        for (int n = 0; n < 4; n++) { c0[n] = c1[n] = c2[n] = c3[n] = 0.f; }

        #pragma unroll
        for (int k0 = 0; k0 < 96; k0 += 16) {
            uint32_t koff = (uint32_t)k0 * 2u;
            uint32_t ah[4], al[4], b0h[4], b1h[4], b0l[4], b1l[4];
            ldsm_x4(ah[0], ah[1], ah[2], ah[3], aOffH + koff);
            ldsm_x4(al[0], al[1], al[2], al[3], aOffL + koff);
            ldsm_x4(b0h[0], b0h[1], b0h[2], b0h[3], bOff0H + koff);
            ldsm_x4(b1h[0], b1h[1], b1h[2], b1h[3], bOff1H + koff);
            ldsm_x4(b0l[0], b0l[1], b0l[2], b0l[3], bOff0L + koff);
            ldsm_x4(b1l[0], b1l[1], b1l[2], b1l[3], bOff1L + koff);
            // tile 0: b regs (b0h[0], b0h[1]); tile 1: (b0h[2], b0h[3]); tiles 2,3 from b1*
            mma_bf16(c0[0], c1[0], c2[0], c3[0], ah[0], ah[1], ah[2], ah[3], b0h[0], b0h[1]);
            mma_bf16(c0[0], c1[0], c2[0], c3[0], ah[0], ah[1], ah[2], ah[3], b0l[0], b0l[1]);
            mma_bf16(c0[0], c1[0], c2[0], c3[0], al[0], al[1], al[2], al[3], b0h[0], b0h[1]);
            mma_bf16(c0[1], c1[1], c2[1], c3[1], ah[0], ah[1], ah[2], ah[3], b0h[2], b0h[3]);
            mma_bf16(c0[1], c1[1], c2[1], c3[1], ah[0], ah[1], ah[2], ah[3], b0l[2], b0l[3]);
            mma_bf16(c0[1], c1[1], c2[1], c3[1], al[0], al[1], al[2], al[3], b0h[2], b0h[3]);
            mma_bf16(c0[2], c1[2], c2[2], c3[2], ah[0], ah[1], ah[2], ah[3], b1h[0], b1h[1]);
            mma_bf16(c0[2], c1[2], c2[2], c3[2], ah[0], ah[1], ah[2], ah[3], b1l[0], b1l[1]);
            mma_bf16(c0[2], c1[2], c2[2], c3[2], al[0], al[1], al[2], al[3], b1h[0], b1h[1]);
            mma_bf16(c0[3], c1[3], c2[3], c3[3], ah[0], ah[1], ah[2], ah[3], b1h[2], b1h[3]);
            mma_bf16(c0[3], c1[3], c2[3], c3[3], ah[0], ah[1], ah[2], ah[3], b1l[2], b1l[3]);
            mma_bf16(c0[3], c1[3], c2[3], c3[3], al[0], al[1], al[2], al[3], b1h[2], b1h[3]);
        }
        // ---- epilogue ----
        int row0 = y0 + mt * 16 + g;
        int row1 = row0 + 8;
        #pragma unroll
        for (int nl = 0; nl < 4; nl++) {
            int col = (nh * 4 + nl) * 8 + 2 * tg;
            float b0v = bias[col], b1v = bias[col + 1];
            float z0 = c0[nl] + b0v, z1 = c1[nl] + b1v;
            float z2 = c2[nl] + b0v, z3 = c3[nl] + b1v;
            z0 = z0 / (1.0f + __expf(-z0));
            z1 = z1 / (1.0f + __expf(-z1));
            z2 = z2 / (1.0f + __expf(-z2));
            z3 = z3 / (1.0f + __expf(-z3));
            *(float2*)&orow[(size_t)row0 * 64 + col] = make_float2(z0, z1);
            *(float2*)&orow[(size_t)row1 * 64 + col] = make_float2(z2, z3);
        }
    }
}

// ---------------- launch ----------------
extern "C" void kernel_launch(void* const* d_in, const int* in_sizes, int n_in,
                              void* d_out, int out_size) {
    const float* X    = (const float*)d_in[0];
    const float* Wres = (const float*)d_in[1];
    const float* bres = (const float*)d_in[2];
    const float* fw0  = (const float*)d_in[3];
    const float* fw1  = (const float*)d_in[4];
    float* out = (float*)d_out;

    const int kE_smem = 4 * 64 * KA_ST * 2 + 64 * 4;   // 53504 B
    cudaFuncSetAttribute(kE, cudaFuncAttributeMaxDynamicSharedMemorySize, kE_smem);

    init_tables<<<96, 256>>>();
    kA2<<<dim3(64, NB), 256>>>(X);
    kB2<<<dim3(128, 2), 128>>>();
    kC4<<<dim3(32, 8), 256>>>(fw0, fw1);
    kD<<<NB * CO, 256>>>();
    kE<<<NB * RR, 256, kE_smem>>>(X, Wres, bres, out);
}

// round 17
// speedup vs baseline: 1.5895x; 1.1946x over previous
#include <cuda_runtime.h>
#include <cuda_bf16.h>
#include <math.h>
#include <stdint.h>

#define NB 8
#define RR 256
#define CI 64
#define CO 64
#define MODES 16
#define KX 32
#define GSZ (NB * KX * MODES * CI)   // 262144
#define HSZ (NB * CO * KX * MODES)   // 262144

// ---------------- f32x2 helpers ----------------
__device__ __forceinline__ unsigned long long f2pack(float a, float b) {
    unsigned long long r;
    asm("mov.b64 %0, {%1, %2};" : "=l"(r) : "f"(a), "f"(b));
    return r;
}
__device__ __forceinline__ void f2unpack(unsigned long long v, float& a, float& b) {
    asm("mov.b64 {%0, %1}, %2;" : "=f"(a), "=f"(b) : "l"(v));
}
__device__ __forceinline__ void ffma2(unsigned long long& d, unsigned long long a,
                                      unsigned long long b) {
    asm("fma.rn.f32x2 %0, %1, %2, %3;" : "=l"(d) : "l"(a), "l"(b), "l"(d));
}

// ---------------- bf16 / mma helpers ----------------
__device__ __forceinline__ uint32_t bf2pack(float lo, float hi) {
    uint32_t r;
    asm("cvt.rn.bf16x2.f32 %0, %1, %2;" : "=r"(r) : "f"(hi), "f"(lo));
    return r;
}
__device__ __forceinline__ void mma_bf16(float& c0, float& c1, float& c2, float& c3,
                                         uint32_t a0, uint32_t a1, uint32_t a2, uint32_t a3,
                                         uint32_t b0, uint32_t b1) {
    asm("mma.sync.aligned.m16n8k16.row.col.f32.bf16.bf16.f32 "
        "{%0,%1,%2,%3}, {%4,%5,%6,%7}, {%8,%9}, {%0,%1,%2,%3};"
        : "+f"(c0), "+f"(c1), "+f"(c2), "+f"(c3)
        : "r"(a0), "r"(a1), "r"(a2), "r"(a3), "r"(b0), "r"(b1));
}
__device__ __forceinline__ void ldsm_x4(uint32_t& r0, uint32_t& r1, uint32_t& r2,
                                        uint32_t& r3, uint32_t addr) {
    asm volatile("ldmatrix.sync.aligned.m8n8.x4.shared.b16 {%0,%1,%2,%3}, [%4];"
                 : "=r"(r0), "=r"(r1), "=r"(r2), "=r"(r3) : "r"(addr));
}

// ---------------- device scratch ----------------
__device__ __align__(16) float g_Fx [64 * 256];
__device__ __align__(16) float g_FxB[256 * 96];
__device__ __align__(16) float g_Wy2[256 * 32];
__device__ __align__(16) float g_T   [2 * 2097152];
__device__ __align__(16) float g_GreP[2 * GSZ];
__device__ __align__(16) float g_GimP[2 * GSZ];
__device__ __align__(16) float g_HreP[4 * HSZ];
__device__ __align__(16) float g_HimP[4 * HSZ];
// packed bf16x2 tables
__device__ __align__(16) uint32_t g_WTh[64 * 32];          // [o][k-pair] hi
__device__ __align__(16) uint32_t g_WTl[64 * 32];          // lo
__device__ __align__(16) uint32_t g_WyETh[256 * 16];       // [y][kk-pair] hi
__device__ __align__(16) uint32_t g_WyETl[256 * 16];
__device__ __align__(16) uint32_t g_Vh[NB * RR * CO * 16]; // [b][x][o][kk-pair]
__device__ __align__(16) uint32_t g_Vl[NB * RR * CO * 16];

// ---------------- table init ----------------
__global__ void init_tables(const float* __restrict__ Wres) {
    int t = blockIdx.x * blockDim.x + threadIdx.x;   // < 24576
    if (t < 64 * 256) {
        int m = t >> 8, x = t & 255;
        int j = m & 31;
        int kx = (j < 16) ? j : (224 + j);
        float s, c;
        sincospif((float)((kx * x) & 255) * (1.0f / 128.0f), &s, &c);
        g_Fx[t] = (m < 32) ? c : -s;
    }
    if (t < 256 * 96) {
        int x = t / 96, m = t % 96;
        int j = m & 31;
        int kx = (j < 16) ? j : (224 + j);
        float s, c;
        sincospif((float)((kx * x) & 255) * (1.0f / 128.0f), &s, &c);
        g_FxB[t] = (m < 32) ? c : ((m < 64) ? s : -s);
    }
    if (t < 256 * 32) {
        int y = t >> 5, kk = t & 31;
        int ky = kk & 15;
        float s, c;
        sincospif((float)((ky * y) & 255) * (1.0f / 128.0f), &s, &c);
        g_Wy2[t] = (kk < 16) ? c : -s;
    }
    if (t < 256 * 16) {                                // WyET bf16 [y][kk-pair]
        int y = t >> 4, q = t & 15;
        float v[2];
        #pragma unroll
        for (int u = 0; u < 2; u++) {
            int kk = q * 2 + u;
            int ky = kk & 15;
            float f = (ky == 0) ? 1.0f : 2.0f;
            float s, c;
            sincospif((float)((ky * y) & 255) * (1.0f / 128.0f), &s, &c);
            v[u] = (kk < 16) ? f * c : -f * s;
        }
        uint32_t h = bf2pack(v[0], v[1]);
        float f0 = __uint_as_float(h << 16), f1 = __uint_as_float(h & 0xFFFF0000u);
        g_WyETh[t] = h;
        g_WyETl[t] = bf2pack(v[0] - f0, v[1] - f1);
    }
    if (t < 64 * 32) {                                 // WresT bf16 [o][k-pair]
        int o = t >> 5, kq = t & 31;
        float v0 = Wres[(kq * 2) * 64 + o];
        float v1 = Wres[(kq * 2 + 1) * 64 + o];
        uint32_t h = bf2pack(v0, v1);
        float f0 = __uint_as_float(h << 16), f1 = __uint_as_float(h & 0xFFFF0000u);
        g_WTh[t] = h;
        g_WTl[t] = bf2pack(v0 - f0, v1 - f1);
    }
}

// ---------------- Stage A': y-direction partial DFT ----------------
__global__ __launch_bounds__(256) void kA2(const float* __restrict__ X) {
    int b  = blockIdx.y;
    int x0 = blockIdx.x * 4;
    __shared__ __align__(16) float Xs[4][32][64];
    __shared__ __align__(16) float Wys[32][32];
    int t  = threadIdx.x;
    int xl = t >> 6;
    int tt = t & 63;
    int kg = tt >> 3;
    int cg = tt & 7;
    int kk0 = kg * 4, c0 = cg * 8;

    unsigned long long acc[4][4];
    #pragma unroll
    for (int i = 0; i < 4; i++)
        #pragma unroll
        for (int p = 0; p < 4; p++) acc[i][p] = 0ull;

    for (int ych = 0; ych < 8; ych++) {
        int y0 = ych * 32;
        #pragma unroll
        for (int l = 0; l < 8; l++) {
            int e = t + l * 256;
            int c4 = e & 15, yy = (e >> 4) & 31, xs = e >> 9;
            *(float4*)&Xs[xs][yy][c4 * 4] =
                *(const float4*)&X[((size_t)((b * 256 + x0 + xs)) * 256 + y0 + yy) * 64 + c4 * 4];
        }
        {
            int kk4 = t & 7, yy = t >> 3;
            *(float4*)&Wys[yy][kk4 * 4] = *(const float4*)&g_Wy2[(y0 + yy) * 32 + kk4 * 4];
        }
        __syncthreads();
        #pragma unroll 8
        for (int yy = 0; yy < 32; yy++) {
            float4 a4 = *(float4*)&Wys[yy][kk0];
            unsigned long long pa0 = f2pack(a4.x, a4.x);
            unsigned long long pa1 = f2pack(a4.y, a4.y);
            unsigned long long pa2 = f2pack(a4.z, a4.z);
            unsigned long long pa3 = f2pack(a4.w, a4.w);
            ulonglong2 b01 = *(ulonglong2*)&Xs[xl][yy][c0];
            ulonglong2 b23 = *(ulonglong2*)&Xs[xl][yy][c0 + 4];
            ffma2(acc[0][0], pa0, b01.x); ffma2(acc[0][1], pa0, b01.y);
            ffma2(acc[0][2], pa0, b23.x); ffma2(acc[0][3], pa0, b23.y);
            ffma2(acc[1][0], pa1, b01.x); ffma2(acc[1][1], pa1, b01.y);
            ffma2(acc[1][2], pa1, b23.x); ffma2(acc[1][3], pa1, b23.y);
            ffma2(acc[2][0], pa2, b01.x); ffma2(acc[2][1], pa2, b01.y);
            ffma2(acc[2][2], pa2, b23.x); ffma2(acc[2][3], pa2, b23.y);
            ffma2(acc[3][0], pa3, b01.x); ffma2(acc[3][1], pa3, b01.y);
            ffma2(acc[3][2], pa3, b23.x); ffma2(acc[3][3], pa3, b23.y);
        }
        __syncthreads();
    }
    int x = x0 + xl;
    #pragma unroll
    for (int j = 0; j < 4; j++) {
        int kk = kk0 + j;
        int ky = kk & 15;
        float* dst = (kk < 16 ? g_T : g_T + 2097152) +
                     ((size_t)((b * 16 + ky) * 256 + x)) * 64 + c0;
        float v[8];
        #pragma unroll
        for (int p = 0; p < 4; p++) f2unpack(acc[j][p], v[2 * p], v[2 * p + 1]);
        *(float4*)&dst[0] = make_float4(v[0], v[1], v[2], v[3]);
        *(float4*)&dst[4] = make_float4(v[4], v[5], v[6], v[7]);
    }
}

// ---------------- Stage B': x-direction partial DFT (x-split halves) ----------------
__global__ __launch_bounds__(128) void kB2() {
    int b = blockIdx.x >> 4, ky = blockIdx.x & 15;
    int xh = blockIdx.y;
    __shared__ __align__(16) float Gr[32 * 64];
    __shared__ __align__(16) float Gi[32 * 64];
    __shared__ __align__(16) float Fxs[32 * 96];
    int t = threadIdx.x;
    int jg = t >> 4, cg = t & 15;
    int j0 = jg * 4, c0 = cg * 4;

    const float* G1r = g_T + ((size_t)(b * 16 + ky)) * 256 * 64;
    const float* G1i = g_T + 2097152 + ((size_t)(b * 16 + ky)) * 256 * 64;

    unsigned long long aR[4][2], aI[4][2];
    #pragma unroll
    for (int i = 0; i < 4; i++) { aR[i][0]=aR[i][1]=aI[i][0]=aI[i][1]=0ull; }

    int xbeg = xh * 128;
    for (int x0 = xbeg; x0 < xbeg + 128; x0 += 32) {
        #pragma unroll
        for (int l = 0; l < 4; l++) {
            int e = t + l * 128;
            ((float4*)Gr)[e] = ((const float4*)(G1r + (size_t)x0 * 64))[e];
            ((float4*)Gi)[e] = ((const float4*)(G1i + (size_t)x0 * 64))[e];
        }
        #pragma unroll
        for (int l = 0; l < 6; l++) {
            int e = t + l * 128;
            ((float4*)Fxs)[e] = ((const float4*)(g_FxB + (size_t)x0 * 96))[e];
        }
        __syncthreads();
        #pragma unroll 4
        for (int xx = 0; xx < 32; xx++) {
            float4 cv = *(float4*)&Fxs[xx * 96 + j0];
            float4 sv = *(float4*)&Fxs[xx * 96 + 32 + j0];
            float4 sn = *(float4*)&Fxs[xx * 96 + 64 + j0];
            ulonglong2 grp = *(ulonglong2*)&Gr[xx * 64 + c0];
            ulonglong2 gip = *(ulonglong2*)&Gi[xx * 64 + c0];
            unsigned long long pc[4] = {f2pack(cv.x,cv.x), f2pack(cv.y,cv.y),
                                        f2pack(cv.z,cv.z), f2pack(cv.w,cv.w)};
            unsigned long long ps[4] = {f2pack(sv.x,sv.x), f2pack(sv.y,sv.y),
                                        f2pack(sv.z,sv.z), f2pack(sv.w,sv.w)};
            unsigned long long pn[4] = {f2pack(sn.x,sn.x), f2pack(sn.y,sn.y),
                                        f2pack(sn.z,sn.z), f2pack(sn.w,sn.w)};
            #pragma unroll
            for (int jj = 0; jj < 4; jj++) {
                ffma2(aR[jj][0], pc[jj], grp.x); ffma2(aR[jj][0], ps[jj], gip.x);
                ffma2(aR[jj][1], pc[jj], grp.y); ffma2(aR[jj][1], ps[jj], gip.y);
                ffma2(aI[jj][0], pc[jj], gip.x); ffma2(aI[jj][0], pn[jj], grp.x);
                ffma2(aI[jj][1], pc[jj], gip.y); ffma2(aI[jj][1], pn[jj], grp.y);
            }
        }
        __syncthreads();
    }
    const float sc = 1.0f / 256.0f;
    float* dstR = g_GreP + (size_t)xh * GSZ;
    float* dstI = g_GimP + (size_t)xh * GSZ;
    #pragma unroll
    for (int jj = 0; jj < 4; jj++) {
        int j = j0 + jj;
        int idx = ((b * KX + j) * MODES + ky) * CI + c0;
        float r0, r1, r2, r3, i0, i1, i2, i3;
        f2unpack(aR[jj][0], r0, r1); f2unpack(aR[jj][1], r2, r3);
        f2unpack(aI[jj][0], i0, i1); f2unpack(aI[jj][1], i2, i3);
        *(float4*)&dstR[idx] = make_float4(r0*sc, r1*sc, r2*sc, r3*sc);
        *(float4*)&dstI[idx] = make_float4(i0*sc, i1*sc, i2*sc, i3*sc);
    }
}

// ---------------- Stage C4: channel mixing, 4-way i-split ----------------
// grid (32, 16): j x (bp(0..3) | ih<<2, ih 0..3); block 256 = o(64) x kyg(4)
__global__ __launch_bounds__(256) void kC4(const float* __restrict__ fw0,
                                           const float* __restrict__ fw1) {
    __shared__ __align__(16) float Gsr[16 * 36];
    __shared__ __align__(16) float Gsi[16 * 36];
    int j  = blockIdx.x;
    int bp = blockIdx.y & 3;
    int ih = blockIdx.y >> 2;                // 0..3, 16 i each
    const float* fw = (j < 16) ? fw0 : fw1;
    int jm = j & 15;
    int t = threadIdx.x;
    int o = t & 63, kyg = t >> 6;

    #pragma unroll
    for (int l = 0; l < 2; l++) {
        int e = t + l * 256;                 // 0..511
        int i = e & 15, ky = (e >> 4) & 15, bl = e >> 8;
        int gidx = (((bp * 2 + bl) * KX + j) * MODES + ky) * CI + ih * 16 + i;
        Gsr[i * 36 + ky * 2 + bl] = g_GreP[gidx] + g_GreP[GSZ + gidx];
        Gsi[i * 36 + ky * 2 + bl] = g_GimP[gidx] + g_GimP[GSZ + gidx];
    }
    __syncthreads();

    float accR[2][4] = {}, accI[2][4] = {};
    #pragma unroll 4
    for (int i = 0; i < 16; i++) {
        const float* fwp = fw + (((size_t)((ih * 16 + i) * 64 + o) * 16 + jm) * 32) + kyg * 8;
        float4 w01 = *(const float4*)fwp;
        float4 w23 = *(const float4*)(fwp + 4);
        float4 gA = *(float4*)&Gsr[i * 36 + kyg * 8];
        float4 gB = *(float4*)&Gsr[i * 36 + kyg * 8 + 4];
        float4 hA = *(float4*)&Gsi[i * 36 + kyg * 8];
        float4 hB = *(float4*)&Gsi[i * 36 + kyg * 8 + 4];
        accR[0][0] += gA.x * w01.x - hA.x * w01.y;  accI[0][0] += gA.x * w01.y + hA.x * w01.x;
        accR[1][0] += gA.y * w01.x - hA.y * w01.y;  accI[1][0] += gA.y * w01.y + hA.y * w01.x;
        accR[0][1] += gA.z * w01.z - hA.z * w01.w;  accI[0][1] += gA.z * w01.w + hA.z * w01.z;
        accR[1][1] += gA.w * w01.z - hA.w * w01.w;  accI[1][1] += gA.w * w01.w + hA.w * w01.z;
        accR[0][2] += gB.x * w23.x - hB.x * w23.y;  accI[0][2] += gB.x * w23.y + hB.x * w23.x;
        accR[1][2] += gB.y * w23.x - hB.y * w23.y;  accI[1][2] += gB.y * w23.y + hB.y * w23.x;
        accR[0][3] += gB.z * w23.z - hB.z * w23.w;  accI[0][3] += gB.z * w23.w + hB.z * w23.z;
        accR[1][3] += gB.w * w23.z - hB.w * w23.w;  accI[1][3] += gB.w * w23.w + hB.w * w23.z;
    }
    float* dR = g_HreP + (size_t)ih * HSZ;
    float* dI = g_HimP + (size_t)ih * HSZ;
    #pragma unroll
    for (int bl = 0; bl < 2; bl++) {
        int bg = bp * 2 + bl;
        int hidx = ((bg * CO + o) * KX + j) * MODES + kyg * 4;
        *(float4*)&dR[hidx] = make_float4(accR[bl][0], accR[bl][1], accR[bl][2], accR[bl][3]);
        *(float4*)&dI[hidx] = make_float4(accI[bl][0], accI[bl][1], accI[bl][2], accI[bl][3]);
    }
}

// ---------------- Stage D: inverse x-DFT → packed bf16 V [b][x][o][kk] ----------------
__global__ __launch_bounds__(256) void kD() {
    int o = blockIdx.x & 63, b = blockIdx.x >> 6;
    __shared__ __align__(16) float hr[KX * MODES];
    __shared__ __align__(16) float hi[KX * MODES];
    int t = threadIdx.x;
    int base = (b * CO + o) * KX * MODES;
    float s0, s1;
    s0 = g_HreP[base + t] + g_HreP[HSZ + base + t]
       + g_HreP[2 * HSZ + base + t] + g_HreP[3 * HSZ + base + t];
    s1 = g_HimP[base + t] + g_HimP[HSZ + base + t]
       + g_HimP[2 * HSZ + base + t] + g_HimP[3 * HSZ + base + t];
    hr[t] = s0; hi[t] = s1;
    s0 = g_HreP[base + t + 256] + g_HreP[HSZ + base + t + 256]
       + g_HreP[2 * HSZ + base + t + 256] + g_HreP[3 * HSZ + base + t + 256];
    s1 = g_HimP[base + t + 256] + g_HimP[HSZ + base + t + 256]
       + g_HimP[2 * HSZ + base + t + 256] + g_HimP[3 * HSZ + base + t + 256];
    hr[t + 256] = s0; hi[t + 256] = s1;
    __syncthreads();
    int x = t;
    float vr[16] = {}, vi[16] = {};
    for (int j = 0; j < 32; j++) {
        float c =  g_Fx[j * 256 + x];
        float s = -g_Fx[(32 + j) * 256 + x];
        #pragma unroll
        for (int kv = 0; kv < 4; kv++) {
            float4 ar = *(float4*)&hr[j * 16 + kv * 4];
            float4 ai = *(float4*)&hi[j * 16 + kv * 4];
            vr[kv*4+0] += ar.x * c - ai.x * s;  vi[kv*4+0] += ar.x * s + ai.x * c;
            vr[kv*4+1] += ar.y * c - ai.y * s;  vi[kv*4+1] += ar.y * s + ai.y * c;
            vr[kv*4+2] += ar.z * c - ai.z * s;  vi[kv*4+2] += ar.z * s + ai.z * c;
            vr[kv*4+3] += ar.w * c - ai.w * s;  vi[kv*4+3] += ar.w * s + ai.w * c;
        }
    }
    const float sc = 1.0f / 256.0f;
    uint32_t hq[16], lq[16];
    #pragma unroll
    for (int q = 0; q < 8; q++) {
        float a = vr[2 * q] * sc, bb = vr[2 * q + 1] * sc;
        uint32_t h = bf2pack(a, bb);
        float fa = __uint_as_float(h << 16), fb = __uint_as_float(h & 0xFFFF0000u);
        hq[q] = h; lq[q] = bf2pack(a - fa, bb - fb);
    }
    #pragma unroll
    for (int q = 0; q < 8; q++) {
        float a = vi[2 * q] * sc, bb = vi[2 * q + 1] * sc;
        uint32_t h = bf2pack(a, bb);
        float fa = __uint_as_float(h << 16), fb = __uint_as_float(h & 0xFFFF0000u);
        hq[8 + q] = h; lq[8 + q] = bf2pack(a - fa, bb - fb);
    }
    size_t base4 = ((size_t)((b * 256 + x) * 64 + o)) * 4;
    #pragma unroll
    for (int u = 0; u < 4; u++) {
        ((uint4*)g_Vh)[base4 + u] = make_uint4(hq[4*u], hq[4*u+1], hq[4*u+2], hq[4*u+3]);
        ((uint4*)g_Vl)[base4 + u] = make_uint4(lq[4*u], lq[4*u+1], lq[4*u+2], lq[4*u+3]);
    }
}

// ---------------- Stage E: K=96 GEMM via 3xBF16 m16n8k16 mma + ldmatrix ----------------
#define KA_ST 104
__global__ __launch_bounds__(256) void kE(const float* __restrict__ X,
                                          const float* __restrict__ bres,
                                          float* __restrict__ out) {
    extern __shared__ __align__(16) char smraw[];
    __nv_bfloat16* Ah = (__nv_bfloat16*)smraw;        // [64][104]
    __nv_bfloat16* Al = Ah + 64 * KA_ST;
    __nv_bfloat16* Bh = Al + 64 * KA_ST;              // [64][104]
    __nv_bfloat16* Bl = Bh + 64 * KA_ST;
    float* bias = (float*)(Bl + 64 * KA_ST);          // [64]

    int bi = blockIdx.x;
    int b = bi >> 8, x = bi & 255;
    int t = threadIdx.x;
    int w = t >> 5, lane = t & 31, g = lane >> 2, tg = lane & 3;
    int mt = w & 3, nh = w >> 2;

    // ---- B fill (once): pure copies from precomputed bf16 tables ----
    #pragma unroll
    for (int l = 0; l < 2; l++) {
        int e = t + l * 256;                 // 0..511 : o = e>>3, q4 = e&7
        int o = e >> 3, q4 = e & 7;
        *(uint4*)&Bh[o * KA_ST + q4 * 8] = ((const uint4*)g_WTh)[o * 8 + q4];
        *(uint4*)&Bl[o * KA_ST + q4 * 8] = ((const uint4*)g_WTl)[o * 8 + q4];
    }
    {
        int o = t >> 2, q4 = t & 3;          // 256 threads cover V part
        size_t src = ((size_t)((b * 256 + x) * 64 + o)) * 4 + q4;
        *(uint4*)&Bh[o * KA_ST + 64 + q4 * 8] = ((const uint4*)g_Vh)[src];
        *(uint4*)&Bl[o * KA_ST + 64 + q4 * 8] = ((const uint4*)g_Vl)[src];
    }
    if (t < 64) bias[t] = bres[t];

    const float* Xrow = X   + ((size_t)(b * 256 + x)) * 16384;
    float*       orow = out + ((size_t)(b * 256 + x)) * 16384;

    uint32_t smb = (uint32_t)__cvta_generic_to_shared(smraw);
    uint32_t aOffH = smb + (uint32_t)((mt * 16 + (lane & 15)) * KA_ST +
                                      ((lane & 16) ? 8 : 0)) * 2u;
    uint32_t aOffL = aOffH + (uint32_t)(64 * KA_ST) * 2u;
    uint32_t brow = (uint32_t)(nh * 32 + (lane & 7) + ((lane & 16) ? 8 : 0));
    uint32_t bcol = (lane & 8) ? 8u : 0u;
    uint32_t bOff0H = smb + (uint32_t)(2 * 64 * KA_ST) * 2u + (brow * KA_ST + bcol) * 2u;
    uint32_t bOff1H = bOff0H + (uint32_t)(16 * KA_ST) * 2u;
    uint32_t bOff0L = bOff0H + (uint32_t)(64 * KA_ST) * 2u;
    uint32_t bOff1L = bOff1H + (uint32_t)(64 * KA_ST) * 2u;

    for (int ch = 0; ch < 4; ch++) {
        int y0 = ch * 64;
        __syncthreads();
        // ---- A fill: X part (cols 0..63), inline fp32→bf16 hi/lo ----
        #pragma unroll
        for (int l = 0; l < 4; l++) {
            int e = t + l * 256;
            int yy = e >> 4, k4 = (e & 15) * 4;
            float4 v = *(const float4*)&Xrow[(size_t)(y0 + yy) * 64 + k4];
            uint32_t* ph = (uint32_t*)&Ah[yy * KA_ST + k4];
            uint32_t* pl = (uint32_t*)&Al[yy * KA_ST + k4];
            uint32_t h01 = bf2pack(v.x, v.y);
            uint32_t h23 = bf2pack(v.z, v.w);
            float hx = __uint_as_float(h01 << 16);
            float hy = __uint_as_float(h01 & 0xFFFF0000u);
            float hz = __uint_as_float(h23 << 16);
            float hw = __uint_as_float(h23 & 0xFFFF0000u);
            ph[0] = h01; ph[1] = h23;
            pl[0] = bf2pack(v.x - hx, v.y - hy);
            pl[1] = bf2pack(v.z - hz, v.w - hw);
        }
        // ---- A fill: WyE part (cols 64..95), copy from bf16 table ----
        {
            int yy = t >> 2, q4 = t & 3;     // 256 threads cover it
            *(uint4*)&Ah[yy * KA_ST + 64 + q4 * 8] = ((const uint4*)g_WyETh)[(y0 + yy) * 4 + q4];
            *(uint4*)&Al[yy * KA_ST + 64 + q4 * 8] = ((const uint4*)g_WyETl)[(y0 + yy) * 4 + q4];
        }
        __syncthreads();

        float c0[4], c1[4], c2[4], c3[4];
        #pragma unroll
        for (int n = 0; n < 4; n++) { c0[n] = c1[n] = c2[n] = c3[n] = 0.f; }

        #pragma unroll
        for (int k0 = 0; k0 < 96; k0 += 16) {
            uint32_t koff = (uint32_t)k0 * 2u;
            uint32_t ah[4], al[4], b0h[4], b1h[4], b0l[4], b1l[4];
            ldsm_x4(ah[0], ah[1], ah[2], ah[3], aOffH + koff);
            ldsm_x4(al[0], al[1], al[2], al[3], aOffL + koff);
            ldsm_x4(b0h[0], b0h[1], b0h[2], b0h[3], bOff0H + koff);
            ldsm_x4(b1h[0], b1h[1], b1h[2], b1h[3], bOff1H + koff);
            ldsm_x4(b0l[0], b0l[1], b0l[2], b0l[3], bOff0L + koff);
            ldsm_x4(b1l[0], b1l[1], b1l[2], b1l[3], bOff1L + koff);
            mma_bf16(c0[0], c1[0], c2[0], c3[0], ah[0], ah[1], ah[2], ah[3], b0h[0], b0h[1]);
            mma_bf16(c0[0], c1[0], c2[0], c3[0], ah[0], ah[1], ah[2], ah[3], b0l[0], b0l[1]);
            mma_bf16(c0[0], c1[0], c2[0], c3[0], al[0], al[1], al[2], al[3], b0h[0], b0h[1]);
            mma_bf16(c0[1], c1[1], c2[1], c3[1], ah[0], ah[1], ah[2], ah[3], b0h[2], b0h[3]);
            mma_bf16(c0[1], c1[1], c2[1], c3[1], ah[0], ah[1], ah[2], ah[3], b0l[2], b0l[3]);
            mma_bf16(c0[1], c1[1], c2[1], c3[1], al[0], al[1], al[2], al[3], b0h[2], b0h[3]);
            mma_bf16(c0[2], c1[2], c2[2], c3[2], ah[0], ah[1], ah[2], ah[3], b1h[0], b1h[1]);
            mma_bf16(c0[2], c1[2], c2[2], c3[2], ah[0], ah[1], ah[2], ah[3], b1l[0], b1l[1]);
            mma_bf16(c0[2], c1[2], c2[2], c3[2], al[0], al[1], al[2], al[3], b1h[0], b1h[1]);
            mma_bf16(c0[3], c1[3], c2[3], c3[3], ah[0], ah[1], ah[2], ah[3], b1h[2], b1h[3]);
            mma_bf16(c0[3], c1[3], c2[3], c3[3], ah[0], ah[1], ah[2], ah[3], b1l[2], b1l[3]);
            mma_bf16(c0[3], c1[3], c2[3], c3[3], al[0], al[1], al[2], al[3], b1h[2], b1h[3]);
        }
        // ---- epilogue ----
        int row0 = y0 + mt * 16 + g;
        int row1 = row0 + 8;
        #pragma unroll
        for (int nl = 0; nl < 4; nl++) {
            int col = (nh * 4 + nl) * 8 + 2 * tg;
            float b0v = bias[col], b1v = bias[col + 1];
            float z0 = c0[nl] + b0v, z1 = c1[nl] + b1v;
            float z2 = c2[nl] + b0v, z3 = c3[nl] + b1v;
            z0 = z0 / (1.0f + __expf(-z0));
            z1 = z1 / (1.0f + __expf(-z1));
            z2 = z2 / (1.0f + __expf(-z2));
            z3 = z3 / (1.0f + __expf(-z3));
            *(float2*)&orow[(size_t)row0 * 64 + col] = make_float2(z0, z1);
            *(float2*)&orow[(size_t)row1 * 64 + col] = make_float2(z2, z3);
        }
    }
}

// ---------------- launch ----------------
extern "C" void kernel_launch(void* const* d_in, const int* in_sizes, int n_in,
                              void* d_out, int out_size) {
    const float* X    = (const float*)d_in[0];
    const float* Wres = (const float*)d_in[1];
    const float* bres = (const float*)d_in[2];
    const float* fw0  = (const float*)d_in[3];
    const float* fw1  = (const float*)d_in[4];
    float* out = (float*)d_out;

    const int kE_smem = 4 * 64 * KA_ST * 2 + 64 * 4;   // 53504 B
    cudaFuncSetAttribute(kE, cudaFuncAttributeMaxDynamicSharedMemorySize, kE_smem);

    init_tables<<<96, 256>>>(Wres);
    kA2<<<dim3(64, NB), 256>>>(X);
    kB2<<<dim3(128, 2), 128>>>();
    kC4<<<dim3(32, 16), 256>>>(fw0, fw1);
    kD<<<NB * CO, 256>>>();
    kE<<<NB * RR, 256, kE_smem>>>(X, bres, out);
}